// round 1
// baseline (speedup 1.0000x reference)
#include <cuda_runtime.h>
#include <math.h>

#define SLEN   2048
#define BATCH  2
#define DMODEL 1024
#define NHEAD  16
#define DKH    64
#define NROWS  (SLEN * BATCH)   // 4096

// Scratch (device globals: no allocation allowed)
__device__ float g_q[BATCH * NHEAD * SLEN * DKH];   // [b][h][s][dk]
__device__ float g_k[BATCH * NHEAD * SLEN * DKH];
__device__ float g_v[BATCH * NHEAD * SLEN * DKH];
__device__ float g_ctx[NROWS * DMODEL];             // [s][b][d]

// ---------------------------------------------------------------------------
// GEMM: C[M,N] = A[M,K] @ W[N,K]^T + bias   (both operands K-major / NT)
// MODE 0: C row-major [M,N]
// MODE 1: scatter to BHSD: m = s*B+b, n = h*DK+j -> out[((b*H+h)*S+s)*DK+j]
// Tiles: BM=BN=128, BK=8, 256 threads, 8x8 per thread.
// ---------------------------------------------------------------------------
template <int MODE>
__global__ void __launch_bounds__(256) gemm_nt(
    const float* __restrict__ A, const float* __restrict__ W,
    const float* __restrict__ bias, float* __restrict__ out,
    int M, int N, int K)
{
    __shared__ float As[8][128];   // [k][m]
    __shared__ float Bs[8][128];   // [k][n]

    const int tid = threadIdx.x;
    const int m0 = blockIdx.y * 128;
    const int n0 = blockIdx.x * 128;
    const int ty = tid >> 4;        // 0..15 (m groups)
    const int tx = tid & 15;        // 0..15 (n groups)

    const int lrow = tid >> 1;          // 0..127
    const int lc4  = (tid & 1) * 4;     // 0 or 4

    float acc[8][8];
#pragma unroll
    for (int i = 0; i < 8; i++)
#pragma unroll
        for (int j = 0; j < 8; j++) acc[i][j] = 0.0f;

    const float* aptr = A + (size_t)(m0 + lrow) * K + lc4;
    const float* bptr = W + (size_t)(n0 + lrow) * K + lc4;

    for (int kt = 0; kt < K; kt += 8) {
        float4 av = *(const float4*)(aptr + kt);
        float4 bv = *(const float4*)(bptr + kt);
        As[lc4 + 0][lrow] = av.x; As[lc4 + 1][lrow] = av.y;
        As[lc4 + 2][lrow] = av.z; As[lc4 + 3][lrow] = av.w;
        Bs[lc4 + 0][lrow] = bv.x; Bs[lc4 + 1][lrow] = bv.y;
        Bs[lc4 + 2][lrow] = bv.z; Bs[lc4 + 3][lrow] = bv.w;
        __syncthreads();

#pragma unroll
        for (int k = 0; k < 8; k++) {
            float4 a0 = *(const float4*)&As[k][ty * 4];
            float4 a1 = *(const float4*)&As[k][ty * 4 + 64];
            float4 b0 = *(const float4*)&Bs[k][tx * 4];
            float4 b1 = *(const float4*)&Bs[k][tx * 4 + 64];
            float rm[8] = {a0.x, a0.y, a0.z, a0.w, a1.x, a1.y, a1.z, a1.w};
            float rn[8] = {b0.x, b0.y, b0.z, b0.w, b1.x, b1.y, b1.z, b1.w};
#pragma unroll
            for (int i = 0; i < 8; i++)
#pragma unroll
                for (int j = 0; j < 8; j++)
                    acc[i][j] = fmaf(rm[i], rn[j], acc[i][j]);
        }
        __syncthreads();
    }

#pragma unroll
    for (int i = 0; i < 8; i++) {
        const int m = m0 + ty * 4 + ((i < 4) ? i : (60 + i));
#pragma unroll
        for (int j = 0; j < 8; j++) {
            const int n = n0 + tx * 4 + ((j < 4) ? j : (60 + j));
            const float c = acc[i][j] + bias[n];
            if (MODE == 0) {
                out[(size_t)m * N + n] = c;
            } else {
                const int s = m / BATCH;
                const int b = m % BATCH;
                const int h = n >> 6;
                const int dj = n & 63;
                out[(((size_t)(b * NHEAD + h)) * SLEN + s) * DKH + dj] = c;
            }
        }
    }
}

// ---------------------------------------------------------------------------
// RoPE, in place on [B*H][S][DK]. Each thread handles (i, i+32) pair.
// cos/sin are [S][DK].
// ---------------------------------------------------------------------------
__global__ void rope_kernel(float* __restrict__ x,
                            const float* __restrict__ cs,
                            const float* __restrict__ sn)
{
    const int gid = blockIdx.x * blockDim.x + threadIdx.x;
    const int row = gid >> 5;         // 0 .. B*H*S-1
    const int i   = gid & 31;
    const int s   = row % SLEN;

    float x1 = x[row * 64 + i];
    float x2 = x[row * 64 + i + 32];
    float c1 = cs[s * 64 + i],      s1 = sn[s * 64 + i];
    float c2 = cs[s * 64 + i + 32], s2 = sn[s * 64 + i + 32];
    x[row * 64 + i]      = x1 * c1 - x2 * s1;
    x[row * 64 + i + 32] = x2 * c2 + x1 * s2;
}

// ---------------------------------------------------------------------------
// Causal flash attention. One block = 64 query rows of one (b,h).
// 256 threads as 16x16; thread owns 4 query rows x (4 key cols | 4 dk dims).
// Online softmax with 16-lane shuffle reductions.
// smem: Qs[64][64], KtSt union (Kt [64][68] / P [64][65]), Vs[64][64]
// ---------------------------------------------------------------------------
#define ATTN_SMEM_FLOATS (64 * 64 + 64 * 68 + 64 * 64)

__global__ void __launch_bounds__(256) attn_kernel(
    const float* __restrict__ gq, const float* __restrict__ gk,
    const float* __restrict__ gv, float* __restrict__ ctx)
{
    extern __shared__ float sm[];
    float* Qs   = sm;                       // [r][d]  stride 64
    float* KtSt = sm + 64 * 64;             // Kt [d][c] stride 68 / P [r][c] stride 65
    float* Vs   = sm + 64 * 64 + 64 * 68;   // [c][d]  stride 64

    const int tid = threadIdx.x;
    const int ty = tid >> 4;   // row group
    const int tx = tid & 15;   // col / dim group
    const int qt = blockIdx.x;
    const int bh = blockIdx.y;
    const int b  = bh / NHEAD;
    const int h  = bh % NHEAD;
    const size_t base = (size_t)bh * SLEN * DKH;
    const int q0 = qt * 64;

    // Load Q tile (coalesced)
#pragma unroll
    for (int i = 0; i < 16; i++) {
        int idx = i * 256 + tid;
        int r = idx >> 6, d = idx & 63;
        Qs[r * 64 + d] = gq[base + (size_t)(q0 + r) * 64 + d];
    }

    float o[4][4];
    float m_i[4], l_i[4];
#pragma unroll
    for (int i = 0; i < 4; i++) {
        m_i[i] = -1e30f; l_i[i] = 0.0f;
#pragma unroll
        for (int j = 0; j < 4; j++) o[i][j] = 0.0f;
    }

    for (int kt = 0; kt <= qt; kt++) {
        const int k0 = kt * 64;
        __syncthreads();   // previous PV reads done (also orders Q stores)

        // Load K (transposed into [d][c], stride 68) and V ([c][d])
#pragma unroll
        for (int i = 0; i < 16; i++) {
            int idx = i * 256 + tid;
            int c = idx >> 6, d = idx & 63;
            size_t goff = base + (size_t)(k0 + c) * 64 + d;
            KtSt[d * 68 + c] = gk[goff];
            Vs[c * 64 + d]   = gv[goff];
        }
        __syncthreads();

        // scores: sc[i][j] = sum_d Q[r][d] * K[c][d]
        float sc[4][4];
#pragma unroll
        for (int i = 0; i < 4; i++)
#pragma unroll
            for (int j = 0; j < 4; j++) sc[i][j] = 0.0f;

#pragma unroll 4
        for (int d = 0; d < 64; d++) {
            float4 kv = *(const float4*)&KtSt[d * 68 + tx * 4];
#pragma unroll
            for (int i = 0; i < 4; i++) {
                float qv = Qs[(ty * 4 + i) * 64 + d];
                sc[i][0] = fmaf(qv, kv.x, sc[i][0]);
                sc[i][1] = fmaf(qv, kv.y, sc[i][1]);
                sc[i][2] = fmaf(qv, kv.z, sc[i][2]);
                sc[i][3] = fmaf(qv, kv.w, sc[i][3]);
            }
        }

        // scale + causal mask (only diagonal tile needs the mask)
        const float scale = 0.125f;  // 1/sqrt(64)
        if (kt == qt) {
#pragma unroll
            for (int i = 0; i < 4; i++)
#pragma unroll
                for (int j = 0; j < 4; j++) {
                    float s = sc[i][j] * scale;
                    if (k0 + tx * 4 + j > q0 + ty * 4 + i) s = -1e30f;
                    sc[i][j] = s;
                }
        } else {
#pragma unroll
            for (int i = 0; i < 4; i++)
#pragma unroll
                for (int j = 0; j < 4; j++) sc[i][j] *= scale;
        }

        // row max across 16-lane group
        float rm[4];
#pragma unroll
        for (int i = 0; i < 4; i++)
            rm[i] = fmaxf(fmaxf(sc[i][0], sc[i][1]), fmaxf(sc[i][2], sc[i][3]));
#pragma unroll
        for (int off = 8; off > 0; off >>= 1)
#pragma unroll
            for (int i = 0; i < 4; i++)
                rm[i] = fmaxf(rm[i], __shfl_xor_sync(0xffffffffu, rm[i], off));

        // online softmax update
        float p[4][4], rs[4];
#pragma unroll
        for (int i = 0; i < 4; i++) {
            float mn = fmaxf(m_i[i], rm[i]);
            float al = __expf(m_i[i] - mn);
            m_i[i] = mn;
            l_i[i] *= al;
            rs[i] = 0.0f;
#pragma unroll
            for (int j = 0; j < 4; j++) {
                p[i][j] = __expf(sc[i][j] - mn);
                rs[i] += p[i][j];
            }
#pragma unroll
            for (int j = 0; j < 4; j++) o[i][j] *= al;
        }
#pragma unroll
        for (int off = 8; off > 0; off >>= 1)
#pragma unroll
            for (int i = 0; i < 4; i++)
                rs[i] += __shfl_xor_sync(0xffffffffu, rs[i], off);
#pragma unroll
        for (int i = 0; i < 4; i++) l_i[i] += rs[i];

        __syncthreads();   // all threads done reading Kt before P overwrites it

        // store P [r][c], stride 65
#pragma unroll
        for (int i = 0; i < 4; i++)
#pragma unroll
            for (int j = 0; j < 4; j++)
                KtSt[(ty * 4 + i) * 65 + tx * 4 + j] = p[i][j];
        __syncthreads();

        // PV: o[i][jd] += sum_c P[r][c] * V[c][d]
#pragma unroll 4
        for (int c = 0; c < 64; c++) {
            float4 vv = *(const float4*)&Vs[c * 64 + tx * 4];
#pragma unroll
            for (int i = 0; i < 4; i++) {
                float pv = KtSt[(ty * 4 + i) * 65 + c];
                o[i][0] = fmaf(pv, vv.x, o[i][0]);
                o[i][1] = fmaf(pv, vv.y, o[i][1]);
                o[i][2] = fmaf(pv, vv.z, o[i][2]);
                o[i][3] = fmaf(pv, vv.w, o[i][3]);
            }
        }
    }

    // epilogue: normalize, write context [s][b][d]
#pragma unroll
    for (int i = 0; i < 4; i++) {
        const float inv = 1.0f / l_i[i];
        const int q = q0 + ty * 4 + i;
        float4 r;
        r.x = o[i][0] * inv; r.y = o[i][1] * inv;
        r.z = o[i][2] * inv; r.w = o[i][3] * inv;
        size_t off = ((size_t)q * BATCH + b) * DMODEL + h * 64 + tx * 4;
        *(float4*)&ctx[off] = r;
    }
}

// ---------------------------------------------------------------------------
extern "C" void kernel_launch(void* const* d_in, const int* in_sizes, int n_in,
                              void* d_out, int out_size)
{
    (void)in_sizes; (void)n_in; (void)out_size;
    const float* Q    = (const float*)d_in[0];
    const float* K    = (const float*)d_in[1];
    const float* V    = (const float*)d_in[2];
    const float* W_q  = (const float*)d_in[3];
    const float* b_q  = (const float*)d_in[4];
    const float* W_k  = (const float*)d_in[5];
    const float* b_k  = (const float*)d_in[6];
    const float* W_v  = (const float*)d_in[7];
    const float* b_v  = (const float*)d_in[8];
    const float* W_o  = (const float*)d_in[9];
    const float* b_o  = (const float*)d_in[10];
    const float* qcos = (const float*)d_in[11];
    const float* qsin = (const float*)d_in[12];
    const float* kcos = (const float*)d_in[13];
    const float* ksin = (const float*)d_in[14];
    float* out = (float*)d_out;

    float *gq, *gk, *gv, *gctx;
    cudaGetSymbolAddress((void**)&gq,   g_q);
    cudaGetSymbolAddress((void**)&gk,   g_k);
    cudaGetSymbolAddress((void**)&gv,   g_v);
    cudaGetSymbolAddress((void**)&gctx, g_ctx);

    const int smem_bytes = ATTN_SMEM_FLOATS * sizeof(float);  // 50176
    cudaFuncSetAttribute(attn_kernel,
                         cudaFuncAttributeMaxDynamicSharedMemorySize, smem_bytes);

    dim3 ggrid(DMODEL / 128, NROWS / 128);   // (8, 32)
    gemm_nt<1><<<ggrid, 256>>>(Q, W_q, b_q, gq, NROWS, DMODEL, DMODEL);
    gemm_nt<1><<<ggrid, 256>>>(K, W_k, b_k, gk, NROWS, DMODEL, DMODEL);
    gemm_nt<1><<<ggrid, 256>>>(V, W_v, b_v, gv, NROWS, DMODEL, DMODEL);

    const int rope_threads = BATCH * NHEAD * SLEN * 32;  // 2M
    rope_kernel<<<rope_threads / 256, 256>>>(gq, qcos, qsin);
    rope_kernel<<<rope_threads / 256, 256>>>(gk, kcos, ksin);

    dim3 agrid(SLEN / 64, BATCH * NHEAD);    // (32, 32)
    attn_kernel<<<agrid, 256, smem_bytes>>>(gq, gk, gv, gctx);

    gemm_nt<0><<<ggrid, 256>>>(gctx, W_o, b_o, out, NROWS, DMODEL, DMODEL);
}

// round 3
// speedup vs baseline: 2.2968x; 2.2968x over previous
#include <cuda_runtime.h>
#include <math.h>
#include <cstdint>

#define SLEN   2048
#define BATCH  2
#define DMODEL 1024
#define NHEAD  16
#define DKH    64
#define NROWS  (SLEN * BATCH)   // 4096

// Scratch (device globals: no allocation allowed)
__device__ float g_q[BATCH * NHEAD * SLEN * DKH];   // [b][h][s][dk]
__device__ float g_k[BATCH * NHEAD * SLEN * DKH];
__device__ float g_v[BATCH * NHEAD * SLEN * DKH];
__device__ float g_ctx[NROWS * DMODEL];             // [s][b][d]

// ---------------------------------------------------------------------------
// tf32 helpers (HMMA path — portable PTX, assembles for plain sm_103)
// ---------------------------------------------------------------------------
__device__ __forceinline__ uint32_t f2tf32(float f) {
    uint32_t u;
    asm("cvt.rna.tf32.f32 %0, %1;" : "=r"(u) : "f"(f));
    return u;
}

// mma.m16n8k8 row.col f32 += tf32*tf32
// A frag: a0=[gid,tg] a1=[gid+8,tg] a2=[gid,tg+4] a3=[gid+8,tg+4]
// B frag: b0=[k=tg,n=gid] b1=[k=tg+4,n=gid]
// C frag: c0=[gid,2tg] c1=[gid,2tg+1] c2=[gid+8,2tg] c3=[gid+8,2tg+1]
__device__ __forceinline__ void mma_tf32(float* c, const uint32_t* a,
                                         uint32_t b0, uint32_t b1) {
    asm volatile(
        "mma.sync.aligned.m16n8k8.row.col.f32.tf32.tf32.f32 "
        "{%0,%1,%2,%3}, {%4,%5,%6,%7}, {%8,%9}, {%0,%1,%2,%3};"
        : "+f"(c[0]), "+f"(c[1]), "+f"(c[2]), "+f"(c[3])
        : "r"(a[0]), "r"(a[1]), "r"(a[2]), "r"(a[3]), "r"(b0), "r"(b1));
}

// ===========================================================================
// GEMM: C[M,N] = A[M,K] @ W[N,K]^T + bias (NT). Block 128x128, BK=16.
// 8 warps: warp tile 32(m) x 64(n). tf32 HMMA.
// MODE 0: row-major out [M,N]; MODE 1: scatter to BHSD.
// ===========================================================================
#define GK      1024
#define SSTRIDE 20   // 16 + 4 pad

template <int MODE>
__global__ void __launch_bounds__(256) gemm_tc(
    const float* __restrict__ A, const float* __restrict__ W,
    const float* __restrict__ bias, float* __restrict__ out)
{
    __shared__ uint32_t As[128 * SSTRIDE];
    __shared__ uint32_t Bs[128 * SSTRIDE];

    const int tid = threadIdx.x;
    const int w    = tid >> 5;
    const int lane = tid & 31;
    const int gid  = lane >> 2;
    const int tg   = lane & 3;
    const int wm = w >> 1;        // 0..3
    const int wn = w & 1;         // 0..1
    const int m0 = blockIdx.y * 128;
    const int n0 = blockIdx.x * 128;

    float c[2][8][4];
#pragma unroll
    for (int mt = 0; mt < 2; mt++)
#pragma unroll
        for (int nt = 0; nt < 8; nt++)
#pragma unroll
            for (int j = 0; j < 4; j++) c[mt][nt][j] = 0.0f;

    for (int kk = 0; kk < GK; kk += 16) {
        __syncthreads();
#pragma unroll
        for (int i = 0; i < 2; i++) {
            int idx = i * 256 + tid;
            int row = idx >> 2;
            int c4  = (idx & 3) * 4;
            float4 av = *(const float4*)(A + (size_t)(m0 + row) * GK + kk + c4);
            As[row * SSTRIDE + c4 + 0] = f2tf32(av.x);
            As[row * SSTRIDE + c4 + 1] = f2tf32(av.y);
            As[row * SSTRIDE + c4 + 2] = f2tf32(av.z);
            As[row * SSTRIDE + c4 + 3] = f2tf32(av.w);
            float4 bv = *(const float4*)(W + (size_t)(n0 + row) * GK + kk + c4);
            Bs[row * SSTRIDE + c4 + 0] = f2tf32(bv.x);
            Bs[row * SSTRIDE + c4 + 1] = f2tf32(bv.y);
            Bs[row * SSTRIDE + c4 + 2] = f2tf32(bv.z);
            Bs[row * SSTRIDE + c4 + 3] = f2tf32(bv.w);
        }
        __syncthreads();

#pragma unroll
        for (int ks = 0; ks < 2; ks++) {
            const int k = ks * 8;
            uint32_t a[2][4];
#pragma unroll
            for (int mt = 0; mt < 2; mt++) {
                const int r = (wm * 32 + mt * 16 + gid) * SSTRIDE;
                a[mt][0] = As[r + k + tg];
                a[mt][1] = As[r + 8 * SSTRIDE + k + tg];
                a[mt][2] = As[r + k + tg + 4];
                a[mt][3] = As[r + 8 * SSTRIDE + k + tg + 4];
            }
#pragma unroll
            for (int nt = 0; nt < 8; nt++) {
                const int r = (wn * 64 + nt * 8 + gid) * SSTRIDE;
                uint32_t b0 = Bs[r + k + tg];
                uint32_t b1 = Bs[r + k + tg + 4];
#pragma unroll
                for (int mt = 0; mt < 2; mt++)
                    mma_tf32(c[mt][nt], a[mt], b0, b1);
            }
        }
    }

    // epilogue
#pragma unroll
    for (int mt = 0; mt < 2; mt++) {
        const int r0 = m0 + wm * 32 + mt * 16 + gid;
        const int r1 = r0 + 8;
#pragma unroll
        for (int nt = 0; nt < 8; nt++) {
            const int n = n0 + wn * 64 + nt * 8 + 2 * tg;
            float2 v0, v1;
            v0.x = c[mt][nt][0] + bias[n];
            v0.y = c[mt][nt][1] + bias[n + 1];
            v1.x = c[mt][nt][2] + bias[n];
            v1.y = c[mt][nt][3] + bias[n + 1];
            if (MODE == 0) {
                *(float2*)&out[(size_t)r0 * DMODEL + n] = v0;
                *(float2*)&out[(size_t)r1 * DMODEL + n] = v1;
            } else {
                const int h  = n >> 6;
                const int dj = n & 63;
                const int s0 = r0 >> 1, b0b = r0 & 1;
                const int s1 = r1 >> 1, b1b = r1 & 1;
                *(float2*)&out[(((size_t)(b0b * NHEAD + h)) * SLEN + s0) * DKH + dj] = v0;
                *(float2*)&out[(((size_t)(b1b * NHEAD + h)) * SLEN + s1) * DKH + dj] = v1;
            }
        }
    }
}

// ---------------------------------------------------------------------------
// RoPE, in place on [B*H][S][DK].
// ---------------------------------------------------------------------------
__global__ void rope_kernel(float* __restrict__ x,
                            const float* __restrict__ cs,
                            const float* __restrict__ sn)
{
    const int gid = blockIdx.x * blockDim.x + threadIdx.x;
    const int row = gid >> 5;
    const int i   = gid & 31;
    const int s   = row % SLEN;

    float x1 = x[row * 64 + i];
    float x2 = x[row * 64 + i + 32];
    float c1 = cs[s * 64 + i],      s1 = sn[s * 64 + i];
    float c2 = cs[s * 64 + i + 32], s2 = sn[s * 64 + i + 32];
    x[row * 64 + i]      = x1 * c1 - x2 * s1;
    x[row * 64 + i + 32] = x2 * c2 + x1 * s2;
}

// ===========================================================================
// Causal flash attention on tf32 HMMA.
// Block = 128 threads (4 warps); 64 q-rows per block (16 per warp).
// Key tiles of 64. Q frags in regs; P via warp-private smem roundtrip.
// smem: Ks[64][68] key-major, Vs[64][72] key-major, QP[64][68] (Q then P).
// ===========================================================================
#define KS_STRIDE 68
#define VS_STRIDE 72
#define ATTN_SMEM_BYTES ((64 * KS_STRIDE + 64 * VS_STRIDE + 64 * KS_STRIDE) * 4)

__global__ void __launch_bounds__(128) attn_tc(
    const float* __restrict__ gq, const float* __restrict__ gk,
    const float* __restrict__ gv, float* __restrict__ ctx)
{
    extern __shared__ uint32_t sm[];
    uint32_t* Ks = sm;                                   // [key][d] tf32
    uint32_t* Vs = sm + 64 * KS_STRIDE;                  // [key][d] tf32
    uint32_t* QP = sm + 64 * KS_STRIDE + 64 * VS_STRIDE; // [row][*] tf32

    const int tid  = threadIdx.x;
    const int w    = tid >> 5;
    const int lane = tid & 31;
    const int gid  = lane >> 2;
    const int tg   = lane & 3;
    const int qt = blockIdx.x;
    const int bh = blockIdx.y;
    const int b  = bh / NHEAD;
    const int h  = bh % NHEAD;
    const size_t base = (size_t)bh * SLEN * DKH;
    const int q0   = qt * 64;
    const int qrow = w * 16;

    // Stage Q tile (tf32) then load per-warp A fragments
#pragma unroll
    for (int i = 0; i < 8; i++) {
        int idx = i * 128 + tid;
        int r  = idx >> 4;
        int d4 = (idx & 15) * 4;
        float4 qv = *(const float4*)(gq + base + (size_t)(q0 + r) * 64 + d4);
        QP[r * KS_STRIDE + d4 + 0] = f2tf32(qv.x);
        QP[r * KS_STRIDE + d4 + 1] = f2tf32(qv.y);
        QP[r * KS_STRIDE + d4 + 2] = f2tf32(qv.z);
        QP[r * KS_STRIDE + d4 + 3] = f2tf32(qv.w);
    }
    __syncthreads();

    uint32_t qa[8][4];
#pragma unroll
    for (int kt8 = 0; kt8 < 8; kt8++) {
        const int r = (qrow + gid) * KS_STRIDE + kt8 * 8;
        qa[kt8][0] = QP[r + tg];
        qa[kt8][1] = QP[r + 8 * KS_STRIDE + tg];
        qa[kt8][2] = QP[r + tg + 4];
        qa[kt8][3] = QP[r + 8 * KS_STRIDE + tg + 4];
    }

    float o[8][4];
#pragma unroll
    for (int nt = 0; nt < 8; nt++)
#pragma unroll
        for (int j = 0; j < 4; j++) o[nt][j] = 0.0f;
    float m0r = -1e30f, m1r = -1e30f, l0 = 0.0f, l1 = 0.0f;

    const int r0g = q0 + qrow + gid;
    const int r1g = r0g + 8;

    for (int kt = 0; kt <= qt; kt++) {
        const int k0g = kt * 64;
        __syncthreads();   // previous iteration's Ks/Vs reads complete

        // Fill K and V tiles (tf32)
#pragma unroll
        for (int i = 0; i < 8; i++) {
            int idx = i * 128 + tid;
            int cK = idx >> 4;
            int d4 = (idx & 15) * 4;
            size_t goff = base + (size_t)(k0g + cK) * 64 + d4;
            float4 kv = *(const float4*)(gk + goff);
            Ks[cK * KS_STRIDE + d4 + 0] = f2tf32(kv.x);
            Ks[cK * KS_STRIDE + d4 + 1] = f2tf32(kv.y);
            Ks[cK * KS_STRIDE + d4 + 2] = f2tf32(kv.z);
            Ks[cK * KS_STRIDE + d4 + 3] = f2tf32(kv.w);
            float4 vv = *(const float4*)(gv + goff);
            Vs[cK * VS_STRIDE + d4 + 0] = f2tf32(vv.x);
            Vs[cK * VS_STRIDE + d4 + 1] = f2tf32(vv.y);
            Vs[cK * VS_STRIDE + d4 + 2] = f2tf32(vv.z);
            Vs[cK * VS_STRIDE + d4 + 3] = f2tf32(vv.w);
        }
        __syncthreads();

        // Scores S = Q K^T  (B frag: b0 = K[key=nt*8+gid][d=ks*8+tg])
        float sc[8][4];
#pragma unroll
        for (int nt = 0; nt < 8; nt++)
#pragma unroll
            for (int j = 0; j < 4; j++) sc[nt][j] = 0.0f;

#pragma unroll
        for (int ks = 0; ks < 8; ks++) {
#pragma unroll
            for (int nt = 0; nt < 8; nt++) {
                const int r = (nt * 8 + gid) * KS_STRIDE + ks * 8;
                uint32_t b0 = Ks[r + tg];
                uint32_t b1 = Ks[r + tg + 4];
                mma_tf32(sc[nt], qa[ks], b0, b1);
            }
        }

        // scale + causal mask (diagonal tile only)
        const float scale = 0.125f;
        if (kt == qt) {
#pragma unroll
            for (int nt = 0; nt < 8; nt++) {
                const int col = k0g + nt * 8 + 2 * tg;
                sc[nt][0] = (col     > r0g) ? -1e30f : sc[nt][0] * scale;
                sc[nt][1] = (col + 1 > r0g) ? -1e30f : sc[nt][1] * scale;
                sc[nt][2] = (col     > r1g) ? -1e30f : sc[nt][2] * scale;
                sc[nt][3] = (col + 1 > r1g) ? -1e30f : sc[nt][3] * scale;
            }
        } else {
#pragma unroll
            for (int nt = 0; nt < 8; nt++)
#pragma unroll
                for (int j = 0; j < 4; j++) sc[nt][j] *= scale;
        }

        // row max over owned cols, then across the 4-lane group (tg)
        float mx0 = -1e30f, mx1 = -1e30f;
#pragma unroll
        for (int nt = 0; nt < 8; nt++) {
            mx0 = fmaxf(mx0, fmaxf(sc[nt][0], sc[nt][1]));
            mx1 = fmaxf(mx1, fmaxf(sc[nt][2], sc[nt][3]));
        }
        mx0 = fmaxf(mx0, __shfl_xor_sync(0xffffffffu, mx0, 1));
        mx0 = fmaxf(mx0, __shfl_xor_sync(0xffffffffu, mx0, 2));
        mx1 = fmaxf(mx1, __shfl_xor_sync(0xffffffffu, mx1, 1));
        mx1 = fmaxf(mx1, __shfl_xor_sync(0xffffffffu, mx1, 2));

        const float mn0 = fmaxf(m0r, mx0);
        const float mn1 = fmaxf(m1r, mx1);
        const float al0 = __expf(m0r - mn0);
        const float al1 = __expf(m1r - mn1);
        m0r = mn0; m1r = mn1;

        float rs0 = 0.0f, rs1 = 0.0f;
        const int pbase = (qrow + gid) * KS_STRIDE + 2 * tg;
#pragma unroll
        for (int nt = 0; nt < 8; nt++) {
            float p0 = __expf(sc[nt][0] - mn0);
            float p1 = __expf(sc[nt][1] - mn0);
            float p2 = __expf(sc[nt][2] - mn1);
            float p3 = __expf(sc[nt][3] - mn1);
            rs0 += p0 + p1;
            rs1 += p2 + p3;
            QP[pbase + nt * 8]                     = f2tf32(p0);
            QP[pbase + nt * 8 + 1]                 = f2tf32(p1);
            QP[pbase + nt * 8 + 8 * KS_STRIDE]     = f2tf32(p2);
            QP[pbase + nt * 8 + 8 * KS_STRIDE + 1] = f2tf32(p3);
        }
        rs0 += __shfl_xor_sync(0xffffffffu, rs0, 1);
        rs0 += __shfl_xor_sync(0xffffffffu, rs0, 2);
        rs1 += __shfl_xor_sync(0xffffffffu, rs1, 1);
        rs1 += __shfl_xor_sync(0xffffffffu, rs1, 2);
        l0 = l0 * al0 + rs0;
        l1 = l1 * al1 + rs1;

#pragma unroll
        for (int nt = 0; nt < 8; nt++) {
            o[nt][0] *= al0; o[nt][1] *= al0;
            o[nt][2] *= al1; o[nt][3] *= al1;
        }
        __syncwarp();   // P rows are warp-private: warp-level ordering suffices

        // O += P V  (A frag = P, B frag: b0 = V[key=ks*8+tg][d=nt*8+gid])
#pragma unroll
        for (int ks = 0; ks < 8; ks++) {
            uint32_t pa[4];
            const int pr = (qrow + gid) * KS_STRIDE + ks * 8;
            pa[0] = QP[pr + tg];
            pa[1] = QP[pr + 8 * KS_STRIDE + tg];
            pa[2] = QP[pr + tg + 4];
            pa[3] = QP[pr + 8 * KS_STRIDE + tg + 4];
#pragma unroll
            for (int nt = 0; nt < 8; nt++) {
                uint32_t b0 = Vs[(ks * 8 + tg) * VS_STRIDE + nt * 8 + gid];
                uint32_t b1 = Vs[(ks * 8 + tg + 4) * VS_STRIDE + nt * 8 + gid];
                mma_tf32(o[nt], pa, b0, b1);
            }
        }
    }

    // epilogue: normalize + write ctx [s][b][d]
    const float inv0 = 1.0f / l0;
    const float inv1 = 1.0f / l1;
#pragma unroll
    for (int nt = 0; nt < 8; nt++) {
        const int col = h * 64 + nt * 8 + 2 * tg;
        float2 v0, v1;
        v0.x = o[nt][0] * inv0; v0.y = o[nt][1] * inv0;
        v1.x = o[nt][2] * inv1; v1.y = o[nt][3] * inv1;
        *(float2*)&ctx[((size_t)r0g * BATCH + b) * DMODEL + col] = v0;
        *(float2*)&ctx[((size_t)r1g * BATCH + b) * DMODEL + col] = v1;
    }
}

// ---------------------------------------------------------------------------
extern "C" void kernel_launch(void* const* d_in, const int* in_sizes, int n_in,
                              void* d_out, int out_size)
{
    (void)in_sizes; (void)n_in; (void)out_size;
    const float* Q    = (const float*)d_in[0];
    const float* K    = (const float*)d_in[1];
    const float* V    = (const float*)d_in[2];
    const float* W_q  = (const float*)d_in[3];
    const float* b_q  = (const float*)d_in[4];
    const float* W_k  = (const float*)d_in[5];
    const float* b_k  = (const float*)d_in[6];
    const float* W_v  = (const float*)d_in[7];
    const float* b_v  = (const float*)d_in[8];
    const float* W_o  = (const float*)d_in[9];
    const float* b_o  = (const float*)d_in[10];
    const float* qcos = (const float*)d_in[11];
    const float* qsin = (const float*)d_in[12];
    const float* kcos = (const float*)d_in[13];
    const float* ksin = (const float*)d_in[14];
    float* out = (float*)d_out;

    float *gq, *gk, *gv, *gctx;
    cudaGetSymbolAddress((void**)&gq,   g_q);
    cudaGetSymbolAddress((void**)&gk,   g_k);
    cudaGetSymbolAddress((void**)&gv,   g_v);
    cudaGetSymbolAddress((void**)&gctx, g_ctx);

    cudaFuncSetAttribute(attn_tc,
                         cudaFuncAttributeMaxDynamicSharedMemorySize,
                         ATTN_SMEM_BYTES);

    dim3 ggrid(DMODEL / 128, NROWS / 128);   // (8, 32)
    gemm_tc<1><<<ggrid, 256>>>(Q, W_q, b_q, gq);
    gemm_tc<1><<<ggrid, 256>>>(K, W_k, b_k, gk);
    gemm_tc<1><<<ggrid, 256>>>(V, W_v, b_v, gv);

    const int rope_threads = BATCH * NHEAD * SLEN * 32;  // 2M
    rope_kernel<<<rope_threads / 256, 256>>>(gq, qcos, qsin);
    rope_kernel<<<rope_threads / 256, 256>>>(gk, kcos, ksin);

    dim3 agrid(SLEN / 64, BATCH * NHEAD);    // (32, 32)
    attn_tc<<<agrid, 128, ATTN_SMEM_BYTES>>>(gq, gk, gv, gctx);

    gemm_tc<0><<<ggrid, 256>>>(gctx, W_o, b_o, out);
}

// round 4
// speedup vs baseline: 2.4386x; 1.0617x over previous
#include <cuda_runtime.h>
#include <math.h>
#include <cstdint>

#define SLEN   2048
#define BATCH  2
#define DMODEL 1024
#define NHEAD  16
#define DKH    64
#define NROWS  (SLEN * BATCH)   // 4096

// Scratch (device globals: no allocation allowed)
__device__ float g_q[BATCH * NHEAD * SLEN * DKH];   // [b][h][s][dk]
__device__ float g_k[BATCH * NHEAD * SLEN * DKH];
__device__ float g_v[BATCH * NHEAD * SLEN * DKH];
__device__ float g_ctx[NROWS * DMODEL];             // [s][b][d]

// ---------------------------------------------------------------------------
// tf32 helpers (HMMA path — portable PTX, assembles for plain sm_103)
// ---------------------------------------------------------------------------
__device__ __forceinline__ uint32_t f2tf32(float f) {
    uint32_t u;
    asm("cvt.rna.tf32.f32 %0, %1;" : "=r"(u) : "f"(f));
    return u;
}

// mma.m16n8k8 row.col f32 += tf32*tf32
// A frag: a0=[gid,tg] a1=[gid+8,tg] a2=[gid,tg+4] a3=[gid+8,tg+4]
// B frag: b0=[k=tg,n=gid] b1=[k=tg+4,n=gid]
// C frag: c0=[gid,2tg] c1=[gid,2tg+1] c2=[gid+8,2tg] c3=[gid+8,2tg+1]
__device__ __forceinline__ void mma_tf32(float* c, const uint32_t* a,
                                         uint32_t b0, uint32_t b1) {
    asm volatile(
        "mma.sync.aligned.m16n8k8.row.col.f32.tf32.tf32.f32 "
        "{%0,%1,%2,%3}, {%4,%5,%6,%7}, {%8,%9}, {%0,%1,%2,%3};"
        : "+f"(c[0]), "+f"(c[1]), "+f"(c[2]), "+f"(c[3])
        : "r"(a[0]), "r"(a[1]), "r"(a[2]), "r"(a[3]), "r"(b0), "r"(b1));
}

__device__ __forceinline__ uint4 pack_tf32(float4 v) {
    uint4 u;
    u.x = f2tf32(v.x); u.y = f2tf32(v.y);
    u.z = f2tf32(v.z); u.w = f2tf32(v.w);
    return u;
}

// ===========================================================================
// GEMM: C[M,N] = A[M,K] @ W[N,K]^T + bias (NT). Block 128x128, BK=16.
// 8 warps: warp tile 32(m) x 64(n). tf32 HMMA.
// Software pipeline: next chunk's gmem prefetched into regs during mma.
// MODE 0: row-major out [M,N]; MODE 1: scatter to BHSD.
// ===========================================================================
#define GK      1024
#define NKIT    (GK / 16)   // 64
#define SSTRIDE 20          // 16 + 4 pad

template <int MODE>
__global__ void __launch_bounds__(256) gemm_tc(
    const float* __restrict__ A, const float* __restrict__ W,
    const float* __restrict__ bias, float* __restrict__ out)
{
    __shared__ uint32_t As[128 * SSTRIDE];
    __shared__ uint32_t Bs[128 * SSTRIDE];

    const int tid = threadIdx.x;
    const int w    = tid >> 5;
    const int lane = tid & 31;
    const int gid  = lane >> 2;
    const int tg   = lane & 3;
    const int wm = w >> 1;        // 0..3
    const int wn = w & 1;         // 0..1
    const int m0 = blockIdx.y * 128;
    const int n0 = blockIdx.x * 128;

    const int row0 = tid >> 2;            // 0..63
    const int row1 = row0 + 64;           // 64..127
    const int c4   = (tid & 3) * 4;

    const float* a0p = A + (size_t)(m0 + row0) * GK + c4;
    const float* a1p = A + (size_t)(m0 + row1) * GK + c4;
    const float* b0p = W + (size_t)(n0 + row0) * GK + c4;
    const float* b1p = W + (size_t)(n0 + row1) * GK + c4;

    float c[2][8][4];
#pragma unroll
    for (int mt = 0; mt < 2; mt++)
#pragma unroll
        for (int nt = 0; nt < 8; nt++)
#pragma unroll
            for (int j = 0; j < 4; j++) c[mt][nt][j] = 0.0f;

    // prefetch chunk 0
    float4 ra0 = *(const float4*)(a0p);
    float4 ra1 = *(const float4*)(a1p);
    float4 rb0 = *(const float4*)(b0p);
    float4 rb1 = *(const float4*)(b1p);

    for (int it = 0; it < NKIT; it++) {
        if (it) __syncthreads();    // previous mma done reading smem

        *(uint4*)&As[row0 * SSTRIDE + c4] = pack_tf32(ra0);
        *(uint4*)&As[row1 * SSTRIDE + c4] = pack_tf32(ra1);
        *(uint4*)&Bs[row0 * SSTRIDE + c4] = pack_tf32(rb0);
        *(uint4*)&Bs[row1 * SSTRIDE + c4] = pack_tf32(rb1);
        __syncthreads();

        if (it + 1 < NKIT) {        // prefetch next chunk (overlaps mma)
            const int kc = (it + 1) * 16;
            ra0 = *(const float4*)(a0p + kc);
            ra1 = *(const float4*)(a1p + kc);
            rb0 = *(const float4*)(b0p + kc);
            rb1 = *(const float4*)(b1p + kc);
        }

#pragma unroll
        for (int ks = 0; ks < 2; ks++) {
            const int k = ks * 8;
            uint32_t a[2][4];
#pragma unroll
            for (int mt = 0; mt < 2; mt++) {
                const int r = (wm * 32 + mt * 16 + gid) * SSTRIDE;
                a[mt][0] = As[r + k + tg];
                a[mt][1] = As[r + 8 * SSTRIDE + k + tg];
                a[mt][2] = As[r + k + tg + 4];
                a[mt][3] = As[r + 8 * SSTRIDE + k + tg + 4];
            }
#pragma unroll
            for (int nt = 0; nt < 8; nt++) {
                const int r = (wn * 64 + nt * 8 + gid) * SSTRIDE;
                uint32_t b0 = Bs[r + k + tg];
                uint32_t b1 = Bs[r + k + tg + 4];
#pragma unroll
                for (int mt = 0; mt < 2; mt++)
                    mma_tf32(c[mt][nt], a[mt], b0, b1);
            }
        }
    }

    // epilogue
#pragma unroll
    for (int mt = 0; mt < 2; mt++) {
        const int r0 = m0 + wm * 32 + mt * 16 + gid;
        const int r1 = r0 + 8;
#pragma unroll
        for (int nt = 0; nt < 8; nt++) {
            const int n = n0 + wn * 64 + nt * 8 + 2 * tg;
            float2 v0, v1;
            v0.x = c[mt][nt][0] + bias[n];
            v0.y = c[mt][nt][1] + bias[n + 1];
            v1.x = c[mt][nt][2] + bias[n];
            v1.y = c[mt][nt][3] + bias[n + 1];
            if (MODE == 0) {
                *(float2*)&out[(size_t)r0 * DMODEL + n] = v0;
                *(float2*)&out[(size_t)r1 * DMODEL + n] = v1;
            } else {
                const int h  = n >> 6;
                const int dj = n & 63;
                const int s0 = r0 >> 1, b0b = r0 & 1;
                const int s1 = r1 >> 1, b1b = r1 & 1;
                *(float2*)&out[(((size_t)(b0b * NHEAD + h)) * SLEN + s0) * DKH + dj] = v0;
                *(float2*)&out[(((size_t)(b1b * NHEAD + h)) * SLEN + s1) * DKH + dj] = v1;
            }
        }
    }
}

// ---------------------------------------------------------------------------
// RoPE, in place on [B*H][S][DK].
// ---------------------------------------------------------------------------
__global__ void rope_kernel(float* __restrict__ x,
                            const float* __restrict__ cs,
                            const float* __restrict__ sn)
{
    const int gid = blockIdx.x * blockDim.x + threadIdx.x;
    const int row = gid >> 5;
    const int i   = gid & 31;
    const int s   = row % SLEN;

    float x1 = x[row * 64 + i];
    float x2 = x[row * 64 + i + 32];
    float c1 = cs[s * 64 + i],      s1 = sn[s * 64 + i];
    float c2 = cs[s * 64 + i + 32], s2 = sn[s * 64 + i + 32];
    x[row * 64 + i]      = x1 * c1 - x2 * s1;
    x[row * 64 + i + 32] = x2 * c2 + x1 * s2;
}

// ===========================================================================
// Causal flash attention on tf32 HMMA.
// Block = 256 threads (8 warps); 128 q-rows per block (16 per warp).
// Key tiles of 64. Q frags in regs; P via warp-private smem roundtrip.
// smem: Ks[64][68] key-major, Vs[64][72] key-major, QP[128][68] (Q then P).
// ===========================================================================
#define KS_STRIDE 68
#define VS_STRIDE 72
#define QTILE     128
#define ATTN_SMEM_BYTES ((64 * KS_STRIDE + 64 * VS_STRIDE + QTILE * KS_STRIDE) * 4)

__global__ void __launch_bounds__(256) attn_tc(
    const float* __restrict__ gq, const float* __restrict__ gk,
    const float* __restrict__ gv, float* __restrict__ ctx)
{
    extern __shared__ uint32_t sm[];
    uint32_t* Ks = sm;                                   // [key][d] tf32
    uint32_t* Vs = sm + 64 * KS_STRIDE;                  // [key][d] tf32
    uint32_t* QP = sm + 64 * KS_STRIDE + 64 * VS_STRIDE; // [row][*] tf32

    const int tid  = threadIdx.x;
    const int w    = tid >> 5;
    const int lane = tid & 31;
    const int gid  = lane >> 2;
    const int tg   = lane & 3;
    const int qt = blockIdx.x;
    const int bh = blockIdx.y;
    const int b  = bh / NHEAD;
    const int h  = bh % NHEAD;
    const size_t base = (size_t)bh * SLEN * DKH;
    const int q0   = qt * QTILE;
    const int qrow = w * 16;

    // Stage Q tile (tf32)
#pragma unroll
    for (int i = 0; i < 8; i++) {
        int idx = i * 256 + tid;
        int r  = idx >> 4;
        int d4 = (idx & 15) * 4;
        float4 qv = *(const float4*)(gq + base + (size_t)(q0 + r) * 64 + d4);
        *(uint4*)&QP[r * KS_STRIDE + d4] = pack_tf32(qv);
    }
    __syncthreads();

    uint32_t qa[8][4];
#pragma unroll
    for (int kt8 = 0; kt8 < 8; kt8++) {
        const int r = (qrow + gid) * KS_STRIDE + kt8 * 8;
        qa[kt8][0] = QP[r + tg];
        qa[kt8][1] = QP[r + 8 * KS_STRIDE + tg];
        qa[kt8][2] = QP[r + tg + 4];
        qa[kt8][3] = QP[r + 8 * KS_STRIDE + tg + 4];
    }

    float o[8][4];
#pragma unroll
    for (int nt = 0; nt < 8; nt++)
#pragma unroll
        for (int j = 0; j < 4; j++) o[nt][j] = 0.0f;
    float m0r = -1e30f, m1r = -1e30f, l0 = 0.0f, l1 = 0.0f;

    const int r0g = q0 + qrow + gid;
    const int r1g = r0g + 8;
    const int wrow_max = q0 + qrow + 15;   // warp-uniform max q row

    const int nkt = 2 * qt + 2;
    for (int kt = 0; kt < nkt; kt++) {
        const int k0g = kt * 64;
        __syncthreads();   // previous iteration's Ks/Vs reads complete

        // Fill K and V tiles (tf32), 256 threads x 4 iters
#pragma unroll
        for (int i = 0; i < 4; i++) {
            int idx = i * 256 + tid;
            int cK = idx >> 4;
            int d4 = (idx & 15) * 4;
            size_t goff = base + (size_t)(k0g + cK) * 64 + d4;
            float4 kv = *(const float4*)(gk + goff);
            *(uint4*)&Ks[cK * KS_STRIDE + d4] = pack_tf32(kv);
            float4 vv = *(const float4*)(gv + goff);
            *(uint4*)&Vs[cK * VS_STRIDE + d4] = pack_tf32(vv);
        }
        __syncthreads();

        if (k0g > wrow_max) continue;   // tile fully masked for this warp

        // Scores S = Q K^T  (B frag: b0 = K[key=nt*8+gid][d=ks*8+tg])
        float sc[8][4];
#pragma unroll
        for (int nt = 0; nt < 8; nt++)
#pragma unroll
            for (int j = 0; j < 4; j++) sc[nt][j] = 0.0f;

#pragma unroll
        for (int ks = 0; ks < 8; ks++) {
#pragma unroll
            for (int nt = 0; nt < 8; nt++) {
                const int r = (nt * 8 + gid) * KS_STRIDE + ks * 8;
                uint32_t b0 = Ks[r + tg];
                uint32_t b1 = Ks[r + tg + 4];
                mma_tf32(sc[nt], qa[ks], b0, b1);
            }
        }

        // scale + causal mask (only the two diagonal tiles need it)
        const float scale = 0.125f;
        if (kt >= 2 * qt) {
#pragma unroll
            for (int nt = 0; nt < 8; nt++) {
                const int col = k0g + nt * 8 + 2 * tg;
                sc[nt][0] = (col     > r0g) ? -1e30f : sc[nt][0] * scale;
                sc[nt][1] = (col + 1 > r0g) ? -1e30f : sc[nt][1] * scale;
                sc[nt][2] = (col     > r1g) ? -1e30f : sc[nt][2] * scale;
                sc[nt][3] = (col + 1 > r1g) ? -1e30f : sc[nt][3] * scale;
            }
        } else {
#pragma unroll
            for (int nt = 0; nt < 8; nt++)
#pragma unroll
                for (int j = 0; j < 4; j++) sc[nt][j] *= scale;
        }

        // row max over owned cols, then across the 4-lane group (tg)
        float mx0 = -1e30f, mx1 = -1e30f;
#pragma unroll
        for (int nt = 0; nt < 8; nt++) {
            mx0 = fmaxf(mx0, fmaxf(sc[nt][0], sc[nt][1]));
            mx1 = fmaxf(mx1, fmaxf(sc[nt][2], sc[nt][3]));
        }
        mx0 = fmaxf(mx0, __shfl_xor_sync(0xffffffffu, mx0, 1));
        mx0 = fmaxf(mx0, __shfl_xor_sync(0xffffffffu, mx0, 2));
        mx1 = fmaxf(mx1, __shfl_xor_sync(0xffffffffu, mx1, 1));
        mx1 = fmaxf(mx1, __shfl_xor_sync(0xffffffffu, mx1, 2));

        const float mn0 = fmaxf(m0r, mx0);
        const float mn1 = fmaxf(m1r, mx1);
        const float al0 = __expf(m0r - mn0);
        const float al1 = __expf(m1r - mn1);
        m0r = mn0; m1r = mn1;

        float rs0 = 0.0f, rs1 = 0.0f;
        const int pbase = (qrow + gid) * KS_STRIDE + 2 * tg;
#pragma unroll
        for (int nt = 0; nt < 8; nt++) {
            float p0 = __expf(sc[nt][0] - mn0);
            float p1 = __expf(sc[nt][1] - mn0);
            float p2 = __expf(sc[nt][2] - mn1);
            float p3 = __expf(sc[nt][3] - mn1);
            rs0 += p0 + p1;
            rs1 += p2 + p3;
            uint2 u01; u01.x = f2tf32(p0); u01.y = f2tf32(p1);
            uint2 u23; u23.x = f2tf32(p2); u23.y = f2tf32(p3);
            *(uint2*)&QP[pbase + nt * 8]                 = u01;
            *(uint2*)&QP[pbase + nt * 8 + 8 * KS_STRIDE] = u23;
        }
        rs0 += __shfl_xor_sync(0xffffffffu, rs0, 1);
        rs0 += __shfl_xor_sync(0xffffffffu, rs0, 2);
        rs1 += __shfl_xor_sync(0xffffffffu, rs1, 1);
        rs1 += __shfl_xor_sync(0xffffffffu, rs1, 2);
        l0 = l0 * al0 + rs0;
        l1 = l1 * al1 + rs1;

#pragma unroll
        for (int nt = 0; nt < 8; nt++) {
            o[nt][0] *= al0; o[nt][1] *= al0;
            o[nt][2] *= al1; o[nt][3] *= al1;
        }
        __syncwarp();   // P rows are warp-private: warp-level ordering suffices

        // O += P V  (A frag = P, B frag: b0 = V[key=ks*8+tg][d=nt*8+gid])
#pragma unroll
        for (int ks = 0; ks < 8; ks++) {
            uint32_t pa[4];
            const int pr = (qrow + gid) * KS_STRIDE + ks * 8;
            pa[0] = QP[pr + tg];
            pa[1] = QP[pr + 8 * KS_STRIDE + tg];
            pa[2] = QP[pr + tg + 4];
            pa[3] = QP[pr + 8 * KS_STRIDE + tg + 4];
#pragma unroll
            for (int nt = 0; nt < 8; nt++) {
                uint32_t b0 = Vs[(ks * 8 + tg) * VS_STRIDE + nt * 8 + gid];
                uint32_t b1 = Vs[(ks * 8 + tg + 4) * VS_STRIDE + nt * 8 + gid];
                mma_tf32(o[nt], pa, b0, b1);
            }
        }
    }

    // epilogue: normalize + write ctx [s][b][d]
    const float inv0 = 1.0f / l0;
    const float inv1 = 1.0f / l1;
#pragma unroll
    for (int nt = 0; nt < 8; nt++) {
        const int col = h * 64 + nt * 8 + 2 * tg;
        float2 v0, v1;
        v0.x = o[nt][0] * inv0; v0.y = o[nt][1] * inv0;
        v1.x = o[nt][2] * inv1; v1.y = o[nt][3] * inv1;
        *(float2*)&ctx[((size_t)r0g * BATCH + b) * DMODEL + col] = v0;
        *(float2*)&ctx[((size_t)r1g * BATCH + b) * DMODEL + col] = v1;
    }
}

// ---------------------------------------------------------------------------
extern "C" void kernel_launch(void* const* d_in, const int* in_sizes, int n_in,
                              void* d_out, int out_size)
{
    (void)in_sizes; (void)n_in; (void)out_size;
    const float* Q    = (const float*)d_in[0];
    const float* K    = (const float*)d_in[1];
    const float* V    = (const float*)d_in[2];
    const float* W_q  = (const float*)d_in[3];
    const float* b_q  = (const float*)d_in[4];
    const float* W_k  = (const float*)d_in[5];
    const float* b_k  = (const float*)d_in[6];
    const float* W_v  = (const float*)d_in[7];
    const float* b_v  = (const float*)d_in[8];
    const float* W_o  = (const float*)d_in[9];
    const float* b_o  = (const float*)d_in[10];
    const float* qcos = (const float*)d_in[11];
    const float* qsin = (const float*)d_in[12];
    const float* kcos = (const float*)d_in[13];
    const float* ksin = (const float*)d_in[14];
    float* out = (float*)d_out;

    float *gq, *gk, *gv, *gctx;
    cudaGetSymbolAddress((void**)&gq,   g_q);
    cudaGetSymbolAddress((void**)&gk,   g_k);
    cudaGetSymbolAddress((void**)&gv,   g_v);
    cudaGetSymbolAddress((void**)&gctx, g_ctx);

    cudaFuncSetAttribute(attn_tc,
                         cudaFuncAttributeMaxDynamicSharedMemorySize,
                         ATTN_SMEM_BYTES);

    dim3 ggrid(DMODEL / 128, NROWS / 128);   // (8, 32)
    gemm_tc<1><<<ggrid, 256>>>(Q, W_q, b_q, gq);
    gemm_tc<1><<<ggrid, 256>>>(K, W_k, b_k, gk);
    gemm_tc<1><<<ggrid, 256>>>(V, W_v, b_v, gv);

    const int rope_threads = BATCH * NHEAD * SLEN * 32;  // 2M
    rope_kernel<<<rope_threads / 256, 256>>>(gq, qcos, qsin);
    rope_kernel<<<rope_threads / 256, 256>>>(gk, kcos, ksin);

    dim3 agrid(SLEN / QTILE, BATCH * NHEAD);   // (16, 32)
    attn_tc<<<agrid, 256, ATTN_SMEM_BYTES>>>(gq, gk, gv, gctx);

    gemm_tc<0><<<ggrid, 256>>>(gctx, W_o, b_o, out);
}

// round 5
// speedup vs baseline: 2.7650x; 1.1339x over previous
#include <cuda_runtime.h>
#include <math.h>
#include <cstdint>

#define SLEN   2048
#define BATCH  2
#define DMODEL 1024
#define NHEAD  16
#define DKH    64
#define NROWS  (SLEN * BATCH)   // 4096

// Scratch (device globals: no allocation allowed)
__device__ float g_q[BATCH * NHEAD * SLEN * DKH];   // [b][h][s][dk]
__device__ float g_k[BATCH * NHEAD * SLEN * DKH];
__device__ float g_v[BATCH * NHEAD * SLEN * DKH];
__device__ float g_ctx[NROWS * DMODEL];             // [s][b][d]

// ---------------------------------------------------------------------------
// tf32 helpers (HMMA path — portable PTX, assembles for plain sm_103)
// ---------------------------------------------------------------------------
__device__ __forceinline__ uint32_t f2tf32(float f) {
    uint32_t u;
    asm("cvt.rna.tf32.f32 %0, %1;" : "=r"(u) : "f"(f));
    return u;
}

// mma.m16n8k8 row.col f32 += tf32*tf32
__device__ __forceinline__ void mma_tf32(float* c, const uint32_t* a,
                                         uint32_t b0, uint32_t b1) {
    asm volatile(
        "mma.sync.aligned.m16n8k8.row.col.f32.tf32.tf32.f32 "
        "{%0,%1,%2,%3}, {%4,%5,%6,%7}, {%8,%9}, {%0,%1,%2,%3};"
        : "+f"(c[0]), "+f"(c[1]), "+f"(c[2]), "+f"(c[3])
        : "r"(a[0]), "r"(a[1]), "r"(a[2]), "r"(a[3]), "r"(b0), "r"(b1));
}

__device__ __forceinline__ uint4 pack_tf32(float4 v) {
    uint4 u;
    u.x = f2tf32(v.x); u.y = f2tf32(v.y);
    u.z = f2tf32(v.z); u.w = f2tf32(v.w);
    return u;
}

// ===========================================================================
// GEMM: C[M,N] = A[M,K] @ W[N,K]^T + bias (NT). Block 128x128, BK=16.
// 8 warps: warp tile 32(m) x 64(n). tf32 HMMA.
// Double-buffered smem: 1 barrier per K-chunk; LDG overlapped with mma.
// MODE 0: row-major out; MODE 1: BHSD scatter; MODE 2: BHSD scatter + RoPE.
// ===========================================================================
#define GK      1024
#define NKIT    (GK / 16)   // 64
#define SSTRIDE 20          // 16 + 4 pad
#define STG     (128 * SSTRIDE)          // u32 per operand per stage
#define GEMM_SMEM_BYTES (4 * STG * 4)    // 2 stages x (A+B) = 40960 B

template <int MODE>
__global__ void __launch_bounds__(256) gemm_tc(
    const float* __restrict__ A, const float* __restrict__ W,
    const float* __restrict__ bias, float* __restrict__ out,
    const float* __restrict__ gcos, const float* __restrict__ gsin)
{
    extern __shared__ uint32_t gsm[];   // [stage][A|B][STG]

    const int tid = threadIdx.x;
    const int w    = tid >> 5;
    const int lane = tid & 31;
    const int gid  = lane >> 2;
    const int tg   = lane & 3;
    const int wm = w >> 1;        // 0..3
    const int wn = w & 1;         // 0..1
    const int m0 = blockIdx.y * 128;
    const int n0 = blockIdx.x * 128;

    const int row0 = tid >> 2;            // 0..63
    const int row1 = row0 + 64;           // 64..127
    const int c4   = (tid & 3) * 4;

    const float* a0p = A + (size_t)(m0 + row0) * GK + c4;
    const float* a1p = A + (size_t)(m0 + row1) * GK + c4;
    const float* b0p = W + (size_t)(n0 + row0) * GK + c4;
    const float* b1p = W + (size_t)(n0 + row1) * GK + c4;

    float c[2][8][4];
#pragma unroll
    for (int mt = 0; mt < 2; mt++)
#pragma unroll
        for (int nt = 0; nt < 8; nt++)
#pragma unroll
            for (int j = 0; j < 4; j++) c[mt][nt][j] = 0.0f;

    // prologue: chunk 0 -> stage 0
    {
        float4 ra0 = *(const float4*)(a0p);
        float4 ra1 = *(const float4*)(a1p);
        float4 rb0 = *(const float4*)(b0p);
        float4 rb1 = *(const float4*)(b1p);
        uint32_t* As0 = gsm;
        uint32_t* Bs0 = gsm + STG;
        *(uint4*)&As0[row0 * SSTRIDE + c4] = pack_tf32(ra0);
        *(uint4*)&As0[row1 * SSTRIDE + c4] = pack_tf32(ra1);
        *(uint4*)&Bs0[row0 * SSTRIDE + c4] = pack_tf32(rb0);
        *(uint4*)&Bs0[row1 * SSTRIDE + c4] = pack_tf32(rb1);
    }
    __syncthreads();

    for (int it = 0; it < NKIT; it++) {
        const int cur = it & 1;
        uint32_t* As = gsm + cur * 2 * STG;
        uint32_t* Bs = As + STG;

        float4 ra0, ra1, rb0, rb1;
        const bool have_next = (it + 1 < NKIT);
        if (have_next) {
            const int kc = (it + 1) * 16;
            ra0 = *(const float4*)(a0p + kc);
            ra1 = *(const float4*)(a1p + kc);
            rb0 = *(const float4*)(b0p + kc);
            rb1 = *(const float4*)(b1p + kc);
        }

#pragma unroll
        for (int ks = 0; ks < 2; ks++) {
            const int k = ks * 8;
            uint32_t a[2][4];
#pragma unroll
            for (int mt = 0; mt < 2; mt++) {
                const int r = (wm * 32 + mt * 16 + gid) * SSTRIDE;
                a[mt][0] = As[r + k + tg];
                a[mt][1] = As[r + 8 * SSTRIDE + k + tg];
                a[mt][2] = As[r + k + tg + 4];
                a[mt][3] = As[r + 8 * SSTRIDE + k + tg + 4];
            }
#pragma unroll
            for (int nt = 0; nt < 8; nt++) {
                const int r = (wn * 64 + nt * 8 + gid) * SSTRIDE;
                uint32_t b0 = Bs[r + k + tg];
                uint32_t b1 = Bs[r + k + tg + 4];
#pragma unroll
                for (int mt = 0; mt < 2; mt++)
                    mma_tf32(c[mt][nt], a[mt], b0, b1);
            }
        }

        if (have_next) {
            uint32_t* Asn = gsm + (cur ^ 1) * 2 * STG;
            uint32_t* Bsn = Asn + STG;
            *(uint4*)&Asn[row0 * SSTRIDE + c4] = pack_tf32(ra0);
            *(uint4*)&Asn[row1 * SSTRIDE + c4] = pack_tf32(ra1);
            *(uint4*)&Bsn[row0 * SSTRIDE + c4] = pack_tf32(rb0);
            *(uint4*)&Bsn[row1 * SSTRIDE + c4] = pack_tf32(rb1);
        }
        __syncthreads();
    }

    if (MODE == 2) {
        // Stage cos/sin for this block's 64 s-values: contiguous 4096 floats
        // each, starting at s_base*64. Reuse the (now free) gemm smem.
        float* rb = (float*)gsm;            // cs: [0,4096), sn: [4096,8192)
        const int s_base = m0 >> 1;
        float4* cs4 = (float4*)rb;
        float4* sn4 = (float4*)(rb + 4096);
#pragma unroll
        for (int i = 0; i < 4; i++) {
            const int idx = i * 256 + tid;  // 0..1023 float4s
            cs4[idx] = *(const float4*)&gcos[(size_t)s_base * 64 + idx * 4];
            sn4[idx] = *(const float4*)&gsin[(size_t)s_base * 64 + idx * 4];
        }
        __syncthreads();
        const float* cs_s = rb;
        const float* sn_s = rb + 4096;

        const int h = (n0 + wn * 64) >> 6;   // one head per wn half
#pragma unroll
        for (int mt = 0; mt < 2; mt++) {
            const int rl0 = wm * 32 + mt * 16 + gid;   // local row
            const int rl1 = rl0 + 8;
            const int r0 = m0 + rl0;
            const int r1 = m0 + rl1;
            const int sl0 = rl0 >> 1;
            const int sl1 = rl1 >> 1;
            const int s0 = r0 >> 1, b0b = r0 & 1;
            const int s1 = r1 >> 1, b1b = r1 & 1;
            const size_t o0 = (((size_t)(b0b * NHEAD + h)) * SLEN + s0) * DKH;
            const size_t o1 = (((size_t)(b1b * NHEAD + h)) * SLEN + s1) * DKH;
#pragma unroll
            for (int nt = 0; nt < 4; nt++) {
                const int dj = nt * 8 + 2 * tg;        // 0..31
                const int n  = n0 + wn * 64 + dj;
                const float bl0 = bias[n],      bl1 = bias[n + 1];
                const float bh0 = bias[n + 32], bh1 = bias[n + 33];

                const float cA0 = cs_s[sl0 * 64 + dj],      cA1 = cs_s[sl0 * 64 + dj + 1];
                const float sA0 = sn_s[sl0 * 64 + dj],      sA1 = sn_s[sl0 * 64 + dj + 1];
                const float cB0 = cs_s[sl0 * 64 + dj + 32], cB1 = cs_s[sl0 * 64 + dj + 33];
                const float sB0 = sn_s[sl0 * 64 + dj + 32], sB1 = sn_s[sl0 * 64 + dj + 33];

                // row r0
                {
                    const float x10 = c[mt][nt][0] + bl0;
                    const float x11 = c[mt][nt][1] + bl1;
                    const float x20 = c[mt][nt + 4][0] + bh0;
                    const float x21 = c[mt][nt + 4][1] + bh1;
                    float2 lo, hi;
                    lo.x = x10 * cA0 - x20 * sA0;
                    lo.y = x11 * cA1 - x21 * sA1;
                    hi.x = x20 * cB0 + x10 * sB0;
                    hi.y = x21 * cB1 + x11 * sB1;
                    *(float2*)&out[o0 + dj]      = lo;
                    *(float2*)&out[o0 + dj + 32] = hi;
                }
                // row r1
                {
                    const float cC0 = cs_s[sl1 * 64 + dj],      cC1 = cs_s[sl1 * 64 + dj + 1];
                    const float sC0 = sn_s[sl1 * 64 + dj],      sC1 = sn_s[sl1 * 64 + dj + 1];
                    const float cD0 = cs_s[sl1 * 64 + dj + 32], cD1 = cs_s[sl1 * 64 + dj + 33];
                    const float sD0 = sn_s[sl1 * 64 + dj + 32], sD1 = sn_s[sl1 * 64 + dj + 33];
                    const float x10 = c[mt][nt][2] + bl0;
                    const float x11 = c[mt][nt][3] + bl1;
                    const float x20 = c[mt][nt + 4][2] + bh0;
                    const float x21 = c[mt][nt + 4][3] + bh1;
                    float2 lo, hi;
                    lo.x = x10 * cC0 - x20 * sC0;
                    lo.y = x11 * cC1 - x21 * sC1;
                    hi.x = x20 * cD0 + x10 * sD0;
                    hi.y = x21 * cD1 + x11 * sD1;
                    *(float2*)&out[o1 + dj]      = lo;
                    *(float2*)&out[o1 + dj + 32] = hi;
                }
            }
        }
        return;
    }

    // epilogue (MODE 0 / 1)
#pragma unroll
    for (int mt = 0; mt < 2; mt++) {
        const int r0 = m0 + wm * 32 + mt * 16 + gid;
        const int r1 = r0 + 8;
#pragma unroll
        for (int nt = 0; nt < 8; nt++) {
            const int n = n0 + wn * 64 + nt * 8 + 2 * tg;
            float2 v0, v1;
            v0.x = c[mt][nt][0] + bias[n];
            v0.y = c[mt][nt][1] + bias[n + 1];
            v1.x = c[mt][nt][2] + bias[n];
            v1.y = c[mt][nt][3] + bias[n + 1];
            if (MODE == 0) {
                *(float2*)&out[(size_t)r0 * DMODEL + n] = v0;
                *(float2*)&out[(size_t)r1 * DMODEL + n] = v1;
            } else {
                const int h  = n >> 6;
                const int dj = n & 63;
                const int s0 = r0 >> 1, b0b = r0 & 1;
                const int s1 = r1 >> 1, b1b = r1 & 1;
                *(float2*)&out[(((size_t)(b0b * NHEAD + h)) * SLEN + s0) * DKH + dj] = v0;
                *(float2*)&out[(((size_t)(b1b * NHEAD + h)) * SLEN + s1) * DKH + dj] = v1;
            }
        }
    }
}

// ===========================================================================
// Causal flash attention on tf32 HMMA.
// Block = 256 threads (8 warps); 128 q-rows per block (16 per warp).
// Double-buffered 64-key K/V tiles: 1 barrier per tile, LDG overlapped
// with mma. Q frags in regs; P via warp-private smem roundtrip.
// ===========================================================================
#define KS_STRIDE 68
#define VS_STRIDE 72
#define QTILE     128
#define KS_SZ     (64 * KS_STRIDE)   // u32 per K stage
#define VS_SZ     (64 * VS_STRIDE)   // u32 per V stage
#define ATTN_SMEM_BYTES ((2 * KS_SZ + 2 * VS_SZ + QTILE * KS_STRIDE) * 4)

__global__ void __launch_bounds__(256) attn_tc(
    const float* __restrict__ gq, const float* __restrict__ gk,
    const float* __restrict__ gv, float* __restrict__ ctx)
{
    extern __shared__ uint32_t sm[];
    uint32_t* KsB = sm;                       // [2][64][KS_STRIDE]
    uint32_t* VsB = sm + 2 * KS_SZ;           // [2][64][VS_STRIDE]
    uint32_t* QP  = sm + 2 * KS_SZ + 2 * VS_SZ;  // [128][KS_STRIDE]

    const int tid  = threadIdx.x;
    const int w    = tid >> 5;
    const int lane = tid & 31;
    const int gid  = lane >> 2;
    const int tg   = lane & 3;
    const int qt = blockIdx.x;
    const int bh = blockIdx.y;
    const int b  = bh / NHEAD;
    const int h  = bh % NHEAD;
    const size_t base = (size_t)bh * SLEN * DKH;
    const int q0   = qt * QTILE;
    const int qrow = w * 16;

    const int fcK = tid >> 4;           // fill: key row 0..15 (+16*i)
    const int fd4 = (tid & 15) * 4;     // fill: dim offset

    // Stage Q tile (tf32)
#pragma unroll
    for (int i = 0; i < 8; i++) {
        int idx = i * 256 + tid;
        int r  = idx >> 4;
        int d4 = (idx & 15) * 4;
        float4 qv = *(const float4*)(gq + base + (size_t)(q0 + r) * 64 + d4);
        *(uint4*)&QP[r * KS_STRIDE + d4] = pack_tf32(qv);
    }
    // Fill tile 0 into stage 0
#pragma unroll
    for (int i = 0; i < 4; i++) {
        const int cK = fcK + i * 16;
        size_t goff = base + (size_t)cK * 64 + fd4;
        float4 kv = *(const float4*)(gk + goff);
        float4 vv = *(const float4*)(gv + goff);
        *(uint4*)&KsB[cK * KS_STRIDE + fd4] = pack_tf32(kv);
        *(uint4*)&VsB[cK * VS_STRIDE + fd4] = pack_tf32(vv);
    }
    __syncthreads();

    uint32_t qa[8][4];
#pragma unroll
    for (int kt8 = 0; kt8 < 8; kt8++) {
        const int r = (qrow + gid) * KS_STRIDE + kt8 * 8;
        qa[kt8][0] = QP[r + tg];
        qa[kt8][1] = QP[r + 8 * KS_STRIDE + tg];
        qa[kt8][2] = QP[r + tg + 4];
        qa[kt8][3] = QP[r + 8 * KS_STRIDE + tg + 4];
    }

    float o[8][4];
#pragma unroll
    for (int nt = 0; nt < 8; nt++)
#pragma unroll
        for (int j = 0; j < 4; j++) o[nt][j] = 0.0f;
    float m0r = -1e30f, m1r = -1e30f, l0 = 0.0f, l1 = 0.0f;

    const int r0g = q0 + qrow + gid;
    const int r1g = r0g + 8;
    const int wrow_max = q0 + qrow + 15;   // warp-uniform max q row

    const int nkt = 2 * qt + 2;
    for (int kt = 0; kt < nkt; kt++) {
        const int k0g = kt * 64;
        const int cur = kt & 1;
        const bool have_next = (kt + 1 < nkt);
        const bool compute = (k0g <= wrow_max);
        uint32_t* Ks = KsB + cur * KS_SZ;
        uint32_t* Vs = VsB + cur * VS_SZ;

        // prefetch next K tile (regs) — overlaps QK mma
        float4 kr[4];
        if (have_next) {
            const size_t nb = base + (size_t)(k0g + 64) * 64;
#pragma unroll
            for (int i = 0; i < 4; i++)
                kr[i] = *(const float4*)(gk + nb + (size_t)(fcK + i * 16) * 64 + fd4);
        }

        float sc[8][4];
        if (compute) {
#pragma unroll
            for (int nt = 0; nt < 8; nt++)
#pragma unroll
                for (int j = 0; j < 4; j++) sc[nt][j] = 0.0f;
#pragma unroll
            for (int ks = 0; ks < 8; ks++) {
#pragma unroll
                for (int nt = 0; nt < 8; nt++) {
                    const int r = (nt * 8 + gid) * KS_STRIDE + ks * 8;
                    uint32_t b0 = Ks[r + tg];
                    uint32_t b1 = Ks[r + tg + 4];
                    mma_tf32(sc[nt], qa[ks], b0, b1);
                }
            }
        }

        // store next K, prefetch next V — overlaps softmax + PV
        float4 vr[4];
        if (have_next) {
            uint32_t* Ksn = KsB + (cur ^ 1) * KS_SZ;
#pragma unroll
            for (int i = 0; i < 4; i++)
                *(uint4*)&Ksn[(fcK + i * 16) * KS_STRIDE + fd4] = pack_tf32(kr[i]);
            const size_t nb = base + (size_t)(k0g + 64) * 64;
#pragma unroll
            for (int i = 0; i < 4; i++)
                vr[i] = *(const float4*)(gv + nb + (size_t)(fcK + i * 16) * 64 + fd4);
        }

        if (compute) {
            // scale + causal mask (only the two diagonal tiles need it)
            const float scale = 0.125f;
            if (kt >= 2 * qt) {
#pragma unroll
                for (int nt = 0; nt < 8; nt++) {
                    const int col = k0g + nt * 8 + 2 * tg;
                    sc[nt][0] = (col     > r0g) ? -1e30f : sc[nt][0] * scale;
                    sc[nt][1] = (col + 1 > r0g) ? -1e30f : sc[nt][1] * scale;
                    sc[nt][2] = (col     > r1g) ? -1e30f : sc[nt][2] * scale;
                    sc[nt][3] = (col + 1 > r1g) ? -1e30f : sc[nt][3] * scale;
                }
            } else {
#pragma unroll
                for (int nt = 0; nt < 8; nt++)
#pragma unroll
                    for (int j = 0; j < 4; j++) sc[nt][j] *= scale;
            }

            float mx0 = -1e30f, mx1 = -1e30f;
#pragma unroll
            for (int nt = 0; nt < 8; nt++) {
                mx0 = fmaxf(mx0, fmaxf(sc[nt][0], sc[nt][1]));
                mx1 = fmaxf(mx1, fmaxf(sc[nt][2], sc[nt][3]));
            }
            mx0 = fmaxf(mx0, __shfl_xor_sync(0xffffffffu, mx0, 1));
            mx0 = fmaxf(mx0, __shfl_xor_sync(0xffffffffu, mx0, 2));
            mx1 = fmaxf(mx1, __shfl_xor_sync(0xffffffffu, mx1, 1));
            mx1 = fmaxf(mx1, __shfl_xor_sync(0xffffffffu, mx1, 2));

            const float mn0 = fmaxf(m0r, mx0);
            const float mn1 = fmaxf(m1r, mx1);
            const float al0 = __expf(m0r - mn0);
            const float al1 = __expf(m1r - mn1);
            m0r = mn0; m1r = mn1;

            float rs0 = 0.0f, rs1 = 0.0f;
            const int pbase = (qrow + gid) * KS_STRIDE + 2 * tg;
#pragma unroll
            for (int nt = 0; nt < 8; nt++) {
                float p0 = __expf(sc[nt][0] - mn0);
                float p1 = __expf(sc[nt][1] - mn0);
                float p2 = __expf(sc[nt][2] - mn1);
                float p3 = __expf(sc[nt][3] - mn1);
                rs0 += p0 + p1;
                rs1 += p2 + p3;
                uint2 u01; u01.x = f2tf32(p0); u01.y = f2tf32(p1);
                uint2 u23; u23.x = f2tf32(p2); u23.y = f2tf32(p3);
                *(uint2*)&QP[pbase + nt * 8]                 = u01;
                *(uint2*)&QP[pbase + nt * 8 + 8 * KS_STRIDE] = u23;
            }
            rs0 += __shfl_xor_sync(0xffffffffu, rs0, 1);
            rs0 += __shfl_xor_sync(0xffffffffu, rs0, 2);
            rs1 += __shfl_xor_sync(0xffffffffu, rs1, 1);
            rs1 += __shfl_xor_sync(0xffffffffu, rs1, 2);
            l0 = l0 * al0 + rs0;
            l1 = l1 * al1 + rs1;

#pragma unroll
            for (int nt = 0; nt < 8; nt++) {
                o[nt][0] *= al0; o[nt][1] *= al0;
                o[nt][2] *= al1; o[nt][3] *= al1;
            }
            __syncwarp();   // P rows are warp-private

            // O += P V
#pragma unroll
            for (int ks = 0; ks < 8; ks++) {
                uint32_t pa[4];
                const int pr = (qrow + gid) * KS_STRIDE + ks * 8;
                pa[0] = QP[pr + tg];
                pa[1] = QP[pr + 8 * KS_STRIDE + tg];
                pa[2] = QP[pr + tg + 4];
                pa[3] = QP[pr + 8 * KS_STRIDE + tg + 4];
#pragma unroll
                for (int nt = 0; nt < 8; nt++) {
                    uint32_t b0 = Vs[(ks * 8 + tg) * VS_STRIDE + nt * 8 + gid];
                    uint32_t b1 = Vs[(ks * 8 + tg + 4) * VS_STRIDE + nt * 8 + gid];
                    mma_tf32(o[nt], pa, b0, b1);
                }
            }
        }

        if (have_next) {
            uint32_t* Vsn = VsB + (cur ^ 1) * VS_SZ;
#pragma unroll
            for (int i = 0; i < 4; i++)
                *(uint4*)&Vsn[(fcK + i * 16) * VS_STRIDE + fd4] = pack_tf32(vr[i]);
        }
        __syncthreads();
    }

    // epilogue: normalize + write ctx [s][b][d]
    const float inv0 = 1.0f / l0;
    const float inv1 = 1.0f / l1;
#pragma unroll
    for (int nt = 0; nt < 8; nt++) {
        const int col = h * 64 + nt * 8 + 2 * tg;
        float2 v0, v1;
        v0.x = o[nt][0] * inv0; v0.y = o[nt][1] * inv0;
        v1.x = o[nt][2] * inv1; v1.y = o[nt][3] * inv1;
        *(float2*)&ctx[((size_t)r0g * BATCH + b) * DMODEL + col] = v0;
        *(float2*)&ctx[((size_t)r1g * BATCH + b) * DMODEL + col] = v1;
    }
}

// ---------------------------------------------------------------------------
extern "C" void kernel_launch(void* const* d_in, const int* in_sizes, int n_in,
                              void* d_out, int out_size)
{
    (void)in_sizes; (void)n_in; (void)out_size;
    const float* Q    = (const float*)d_in[0];
    const float* K    = (const float*)d_in[1];
    const float* V    = (const float*)d_in[2];
    const float* W_q  = (const float*)d_in[3];
    const float* b_q  = (const float*)d_in[4];
    const float* W_k  = (const float*)d_in[5];
    const float* b_k  = (const float*)d_in[6];
    const float* W_v  = (const float*)d_in[7];
    const float* b_v  = (const float*)d_in[8];
    const float* W_o  = (const float*)d_in[9];
    const float* b_o  = (const float*)d_in[10];
    const float* qcos = (const float*)d_in[11];
    const float* qsin = (const float*)d_in[12];
    const float* kcos = (const float*)d_in[13];
    const float* ksin = (const float*)d_in[14];
    float* out = (float*)d_out;

    float *gq, *gk, *gv, *gctx;
    cudaGetSymbolAddress((void**)&gq,   g_q);
    cudaGetSymbolAddress((void**)&gk,   g_k);
    cudaGetSymbolAddress((void**)&gv,   g_v);
    cudaGetSymbolAddress((void**)&gctx, g_ctx);

    cudaFuncSetAttribute(attn_tc,
                         cudaFuncAttributeMaxDynamicSharedMemorySize,
                         ATTN_SMEM_BYTES);

    dim3 ggrid(DMODEL / 128, NROWS / 128);   // (8, 32)
    gemm_tc<2><<<ggrid, 256, GEMM_SMEM_BYTES>>>(Q, W_q, b_q, gq, qcos, qsin);
    gemm_tc<2><<<ggrid, 256, GEMM_SMEM_BYTES>>>(K, W_k, b_k, gk, kcos, ksin);
    gemm_tc<1><<<ggrid, 256, GEMM_SMEM_BYTES>>>(V, W_v, b_v, gv, nullptr, nullptr);

    dim3 agrid(SLEN / QTILE, BATCH * NHEAD);   // (16, 32)
    attn_tc<<<agrid, 256, ATTN_SMEM_BYTES>>>(gq, gk, gv, gctx);

    gemm_tc<0><<<ggrid, 256, GEMM_SMEM_BYTES>>>(gctx, W_o, b_o, out, nullptr, nullptr);
}

// round 6
// speedup vs baseline: 3.3237x; 1.2021x over previous
#include <cuda_runtime.h>
#include <math.h>
#include <cstdint>

#define SLEN   2048
#define BATCH  2
#define DMODEL 1024
#define NHEAD  16
#define DKH    64
#define NROWS  (SLEN * BATCH)   // 4096

// Scratch (device globals: no allocation allowed)
__device__ float g_q[BATCH * NHEAD * SLEN * DKH];   // [b][h][s][dk] tf32-rounded
__device__ float g_k[BATCH * NHEAD * SLEN * DKH];
__device__ float g_v[BATCH * NHEAD * SLEN * DKH];
__device__ float g_ctx[NROWS * DMODEL];             // [s][b][d]   tf32-rounded

// ---------------------------------------------------------------------------
// Helpers (portable PTX, assembles for plain sm_103)
// ---------------------------------------------------------------------------
__device__ __forceinline__ uint32_t f2tf32(float f) {
    uint32_t u;
    asm("cvt.rna.tf32.f32 %0, %1;" : "=r"(u) : "f"(f));
    return u;
}
__device__ __forceinline__ float rnd_tf32(float f) {
    return __uint_as_float(f2tf32(f));
}
__device__ __forceinline__ void mma_tf32(float* c, const uint32_t* a,
                                         uint32_t b0, uint32_t b1) {
    asm volatile(
        "mma.sync.aligned.m16n8k8.row.col.f32.tf32.tf32.f32 "
        "{%0,%1,%2,%3}, {%4,%5,%6,%7}, {%8,%9}, {%0,%1,%2,%3};"
        : "+f"(c[0]), "+f"(c[1]), "+f"(c[2]), "+f"(c[3])
        : "r"(a[0]), "r"(a[1]), "r"(a[2]), "r"(a[3]), "r"(b0), "r"(b1));
}
__device__ __forceinline__ uint4 pack_tf32(float4 v) {
    uint4 u;
    u.x = f2tf32(v.x); u.y = f2tf32(v.y);
    u.z = f2tf32(v.z); u.w = f2tf32(v.w);
    return u;
}
__device__ __forceinline__ uint32_t smem_u32(const void* p) {
    uint32_t a;
    asm("{ .reg .u64 t; cvta.to.shared.u64 t, %1; cvt.u32.u64 %0, t; }"
        : "=r"(a) : "l"(p));
    return a;
}
__device__ __forceinline__ void cp_async16(uint32_t saddr, const void* gptr) {
    asm volatile("cp.async.cg.shared.global [%0], [%1], 16;"
                 :: "r"(saddr), "l"(gptr) : "memory");
}
#define CP_ASYNC_COMMIT() asm volatile("cp.async.commit_group;" ::: "memory")
template <int N>
__device__ __forceinline__ void cp_async_wait() {
    asm volatile("cp.async.wait_group %0;" :: "n"(N) : "memory");
}
// ldmatrix m8n8.x4 (b16 rows of 16B; one tf32 element per lane per matrix)
__device__ __forceinline__ void ldsm4(uint32_t* r, uint32_t addr) {
    asm volatile("ldmatrix.sync.aligned.m8n8.x4.shared.b16 {%0,%1,%2,%3}, [%4];"
                 : "=r"(r[0]), "=r"(r[1]), "=r"(r[2]), "=r"(r[3]) : "r"(addr));
}

// ===========================================================================
// GEMM body: C[M,N] = A[M,K] @ W[N,K]^T + bias (NT). Block 128x128, BK=16.
// 8 warps: warp tile 32(m) x 64(n). tf32 HMMA, double-buffered smem.
// MODE 0: row-major out; MODE 1: BHSD scatter (tf32-rounded);
// MODE 2: BHSD scatter + RoPE (tf32-rounded).
// ===========================================================================
#define GK      1024
#define NKIT    (GK / 16)   // 64
#define SSTRIDE 20          // 16 + 4 pad
#define STG     (128 * SSTRIDE)
#define GEMM_SMEM_BYTES (4 * STG * 4)    // 40960 B

template <int MODE>
__device__ __forceinline__ void gemm_body(
    const float* __restrict__ A, const float* __restrict__ W,
    const float* __restrict__ bias, float* __restrict__ out,
    const float* __restrict__ gcos, const float* __restrict__ gsin,
    uint32_t* gsm)
{
    const int tid = threadIdx.x;
    const int w    = tid >> 5;
    const int lane = tid & 31;
    const int gid  = lane >> 2;
    const int tg   = lane & 3;
    const int wm = w >> 1;
    const int wn = w & 1;
    const int m0 = blockIdx.y * 128;
    const int n0 = blockIdx.x * 128;

    const int row0 = tid >> 2;
    const int row1 = row0 + 64;
    const int c4   = (tid & 3) * 4;

    const float* a0p = A + (size_t)(m0 + row0) * GK + c4;
    const float* a1p = A + (size_t)(m0 + row1) * GK + c4;
    const float* b0p = W + (size_t)(n0 + row0) * GK + c4;
    const float* b1p = W + (size_t)(n0 + row1) * GK + c4;

    float c[2][8][4];
#pragma unroll
    for (int mt = 0; mt < 2; mt++)
#pragma unroll
        for (int nt = 0; nt < 8; nt++)
#pragma unroll
            for (int j = 0; j < 4; j++) c[mt][nt][j] = 0.0f;

    {
        float4 ra0 = *(const float4*)(a0p);
        float4 ra1 = *(const float4*)(a1p);
        float4 rb0 = *(const float4*)(b0p);
        float4 rb1 = *(const float4*)(b1p);
        uint32_t* As0 = gsm;
        uint32_t* Bs0 = gsm + STG;
        *(uint4*)&As0[row0 * SSTRIDE + c4] = pack_tf32(ra0);
        *(uint4*)&As0[row1 * SSTRIDE + c4] = pack_tf32(ra1);
        *(uint4*)&Bs0[row0 * SSTRIDE + c4] = pack_tf32(rb0);
        *(uint4*)&Bs0[row1 * SSTRIDE + c4] = pack_tf32(rb1);
    }
    __syncthreads();

    for (int it = 0; it < NKIT; it++) {
        const int cur = it & 1;
        uint32_t* As = gsm + cur * 2 * STG;
        uint32_t* Bs = As + STG;

        float4 ra0, ra1, rb0, rb1;
        const bool have_next = (it + 1 < NKIT);
        if (have_next) {
            const int kc = (it + 1) * 16;
            ra0 = *(const float4*)(a0p + kc);
            ra1 = *(const float4*)(a1p + kc);
            rb0 = *(const float4*)(b0p + kc);
            rb1 = *(const float4*)(b1p + kc);
        }

#pragma unroll
        for (int ks = 0; ks < 2; ks++) {
            const int k = ks * 8;
            uint32_t a[2][4];
#pragma unroll
            for (int mt = 0; mt < 2; mt++) {
                const int r = (wm * 32 + mt * 16 + gid) * SSTRIDE;
                a[mt][0] = As[r + k + tg];
                a[mt][1] = As[r + 8 * SSTRIDE + k + tg];
                a[mt][2] = As[r + k + tg + 4];
                a[mt][3] = As[r + 8 * SSTRIDE + k + tg + 4];
            }
#pragma unroll
            for (int nt = 0; nt < 8; nt++) {
                const int r = (wn * 64 + nt * 8 + gid) * SSTRIDE;
                uint32_t b0 = Bs[r + k + tg];
                uint32_t b1 = Bs[r + k + tg + 4];
#pragma unroll
                for (int mt = 0; mt < 2; mt++)
                    mma_tf32(c[mt][nt], a[mt], b0, b1);
            }
        }

        if (have_next) {
            uint32_t* Asn = gsm + (cur ^ 1) * 2 * STG;
            uint32_t* Bsn = Asn + STG;
            *(uint4*)&Asn[row0 * SSTRIDE + c4] = pack_tf32(ra0);
            *(uint4*)&Asn[row1 * SSTRIDE + c4] = pack_tf32(ra1);
            *(uint4*)&Bsn[row0 * SSTRIDE + c4] = pack_tf32(rb0);
            *(uint4*)&Bsn[row1 * SSTRIDE + c4] = pack_tf32(rb1);
        }
        __syncthreads();
    }

    if (MODE == 2) {
        // Stage cos/sin for this block's 64 s-values (contiguous in gmem)
        float* rb = (float*)gsm;
        const int s_base = m0 >> 1;
        float4* cs4 = (float4*)rb;
        float4* sn4 = (float4*)(rb + 4096);
#pragma unroll
        for (int i = 0; i < 4; i++) {
            const int idx = i * 256 + tid;
            cs4[idx] = *(const float4*)&gcos[(size_t)s_base * 64 + idx * 4];
            sn4[idx] = *(const float4*)&gsin[(size_t)s_base * 64 + idx * 4];
        }
        __syncthreads();
        const float* cs_s = rb;
        const float* sn_s = rb + 4096;

        const int h = (n0 + wn * 64) >> 6;
#pragma unroll
        for (int mt = 0; mt < 2; mt++) {
            const int rl0 = wm * 32 + mt * 16 + gid;
            const int rl1 = rl0 + 8;
            const int r0 = m0 + rl0;
            const int r1 = m0 + rl1;
            const int sl0 = rl0 >> 1;
            const int sl1 = rl1 >> 1;
            const int s0 = r0 >> 1, b0b = r0 & 1;
            const int s1 = r1 >> 1, b1b = r1 & 1;
            const size_t o0 = (((size_t)(b0b * NHEAD + h)) * SLEN + s0) * DKH;
            const size_t o1 = (((size_t)(b1b * NHEAD + h)) * SLEN + s1) * DKH;
#pragma unroll
            for (int nt = 0; nt < 4; nt++) {
                const int dj = nt * 8 + 2 * tg;
                const int n  = n0 + wn * 64 + dj;
                const float bl0 = bias[n],      bl1 = bias[n + 1];
                const float bh0 = bias[n + 32], bh1 = bias[n + 33];

                const float cA0 = cs_s[sl0 * 64 + dj],      cA1 = cs_s[sl0 * 64 + dj + 1];
                const float sA0 = sn_s[sl0 * 64 + dj],      sA1 = sn_s[sl0 * 64 + dj + 1];
                const float cB0 = cs_s[sl0 * 64 + dj + 32], cB1 = cs_s[sl0 * 64 + dj + 33];
                const float sB0 = sn_s[sl0 * 64 + dj + 32], sB1 = sn_s[sl0 * 64 + dj + 33];
                {
                    const float x10 = c[mt][nt][0] + bl0;
                    const float x11 = c[mt][nt][1] + bl1;
                    const float x20 = c[mt][nt + 4][0] + bh0;
                    const float x21 = c[mt][nt + 4][1] + bh1;
                    float2 lo, hi;
                    lo.x = rnd_tf32(x10 * cA0 - x20 * sA0);
                    lo.y = rnd_tf32(x11 * cA1 - x21 * sA1);
                    hi.x = rnd_tf32(x20 * cB0 + x10 * sB0);
                    hi.y = rnd_tf32(x21 * cB1 + x11 * sB1);
                    *(float2*)&out[o0 + dj]      = lo;
                    *(float2*)&out[o0 + dj + 32] = hi;
                }
                {
                    const float cC0 = cs_s[sl1 * 64 + dj],      cC1 = cs_s[sl1 * 64 + dj + 1];
                    const float sC0 = sn_s[sl1 * 64 + dj],      sC1 = sn_s[sl1 * 64 + dj + 1];
                    const float cD0 = cs_s[sl1 * 64 + dj + 32], cD1 = cs_s[sl1 * 64 + dj + 33];
                    const float sD0 = sn_s[sl1 * 64 + dj + 32], sD1 = sn_s[sl1 * 64 + dj + 33];
                    const float x10 = c[mt][nt][2] + bl0;
                    const float x11 = c[mt][nt][3] + bl1;
                    const float x20 = c[mt][nt + 4][2] + bh0;
                    const float x21 = c[mt][nt + 4][3] + bh1;
                    float2 lo, hi;
                    lo.x = rnd_tf32(x10 * cC0 - x20 * sC0);
                    lo.y = rnd_tf32(x11 * cC1 - x21 * sC1);
                    hi.x = rnd_tf32(x20 * cD0 + x10 * sD0);
                    hi.y = rnd_tf32(x21 * cD1 + x11 * sD1);
                    *(float2*)&out[o1 + dj]      = lo;
                    *(float2*)&out[o1 + dj + 32] = hi;
                }
            }
        }
        return;
    }

#pragma unroll
    for (int mt = 0; mt < 2; mt++) {
        const int r0 = m0 + wm * 32 + mt * 16 + gid;
        const int r1 = r0 + 8;
#pragma unroll
        for (int nt = 0; nt < 8; nt++) {
            const int n = n0 + wn * 64 + nt * 8 + 2 * tg;
            float2 v0, v1;
            if (MODE == 0) {
                v0.x = c[mt][nt][0] + bias[n];
                v0.y = c[mt][nt][1] + bias[n + 1];
                v1.x = c[mt][nt][2] + bias[n];
                v1.y = c[mt][nt][3] + bias[n + 1];
                *(float2*)&out[(size_t)r0 * DMODEL + n] = v0;
                *(float2*)&out[(size_t)r1 * DMODEL + n] = v1;
            } else {
                v0.x = rnd_tf32(c[mt][nt][0] + bias[n]);
                v0.y = rnd_tf32(c[mt][nt][1] + bias[n + 1]);
                v1.x = rnd_tf32(c[mt][nt][2] + bias[n]);
                v1.y = rnd_tf32(c[mt][nt][3] + bias[n + 1]);
                const int h  = n >> 6;
                const int dj = n & 63;
                const int s0 = r0 >> 1, b0b = r0 & 1;
                const int s1 = r1 >> 1, b1b = r1 & 1;
                *(float2*)&out[(((size_t)(b0b * NHEAD + h)) * SLEN + s0) * DKH + dj] = v0;
                *(float2*)&out[(((size_t)(b1b * NHEAD + h)) * SLEN + s1) * DKH + dj] = v1;
            }
        }
    }
}

// Fused Q/K/V projections: blockIdx.z selects tensor; Q,K get RoPE.
__global__ void __launch_bounds__(256, 2) gemm_qkv(
    const float* Q, const float* Wq, const float* bq, float* oq,
    const float* K, const float* Wk, const float* bk, float* ok,
    const float* V, const float* Wv, const float* bv, float* ov,
    const float* qcos, const float* qsin,
    const float* kcos, const float* ksin)
{
    extern __shared__ uint32_t gsm[];
    if (blockIdx.z == 0)      gemm_body<2>(Q, Wq, bq, oq, qcos, qsin, gsm);
    else if (blockIdx.z == 1) gemm_body<2>(K, Wk, bk, ok, kcos, ksin, gsm);
    else                      gemm_body<1>(V, Wv, bv, ov, nullptr, nullptr, gsm);
}

__global__ void __launch_bounds__(256, 2) gemm_out(
    const float* A, const float* W, const float* bias, float* out)
{
    extern __shared__ uint32_t gsm[];
    gemm_body<0>(A, W, bias, out, nullptr, nullptr, gsm);
}

// ===========================================================================
// Causal flash attention, tf32 HMMA, cp.async staging (inputs pre-rounded).
// Block = 256 threads (8 warps); 128 q-rows per block (16 per warp).
// 2-stage K/V pipeline; ldmatrix for QK B-frags and P A-frags.
// ===========================================================================
#define KS_STRIDE 68
#define VS_STRIDE 72
#define QTILE     128
#define KS_SZ     (64 * KS_STRIDE)
#define VS_SZ     (64 * VS_STRIDE)
#define QP_OFF    (2 * KS_SZ + 2 * VS_SZ)
#define ATTN_SMEM_BYTES ((QP_OFF + QTILE * KS_STRIDE) * 4)

__global__ void __launch_bounds__(256, 2) attn_tc(
    const float* __restrict__ gq, const float* __restrict__ gk,
    const float* __restrict__ gv, float* __restrict__ ctx)
{
    extern __shared__ uint32_t sm[];
    const uint32_t smb    = smem_u32(sm);
    const uint32_t ks_u   = smb;                      // [2][64][KS_STRIDE]
    const uint32_t vs_u   = smb + 2 * KS_SZ * 4;      // [2][64][VS_STRIDE]
    const uint32_t qp_u   = smb + QP_OFF * 4;         // [128][KS_STRIDE]
    uint32_t* VsB = sm + 2 * KS_SZ;
    uint32_t* QP  = sm + QP_OFF;

    const int tid  = threadIdx.x;
    const int w    = tid >> 5;
    const int lane = tid & 31;
    const int gid  = lane >> 2;
    const int tg   = lane & 3;
    const int qt = (int)gridDim.x - 1 - (int)blockIdx.x;   // heavy tiles first
    const int bh = blockIdx.y;
    const int b  = bh / NHEAD;
    const int h  = bh % NHEAD;
    const size_t base = (size_t)bh * SLEN * DKH;
    const int q0   = qt * QTILE;
    const int qrow = w * 16;

    const int fcK = tid >> 4;           // fill: key row 0..15 (+16*i)
    const int fd4 = (tid & 15) * 4;     // fill: dim offset

    // per-lane ldmatrix bases
    // A-frag (Q/P): rows qrow + (l&7) + ((l>>3)&1)*8 ; dcol ((l>>4)&1)*4
    const uint32_t a_base = qp_u +
        ((qrow + (lane & 7) + ((lane >> 3) & 1) * 8) * KS_STRIDE +
         ((lane >> 4) & 1) * 4) * 4;
    // B-frag (K): key (l&7) + ((l>>4)&1)*8 ; dcol ((l>>3)&1)*4
    const uint32_t kb_base =
        (((lane & 7) + ((lane >> 4) & 1) * 8) * KS_STRIDE +
         ((lane >> 3) & 1) * 4) * 4;

    // ---- prologue: stage Q + tile 0 (group 0) ----
#pragma unroll
    for (int i = 0; i < 8; i++) {
        const int idx = i * 256 + tid;
        const int r  = idx >> 4;
        const int d4 = (idx & 15) * 4;
        cp_async16(qp_u + (r * KS_STRIDE + d4) * 4,
                   gq + base + (size_t)(q0 + r) * 64 + d4);
    }
#pragma unroll
    for (int i = 0; i < 4; i++) {
        const int cK = fcK + i * 16;
        const size_t goff = base + (size_t)cK * 64 + fd4;
        cp_async16(ks_u + (cK * KS_STRIDE + fd4) * 4, gk + goff);
        cp_async16(vs_u + (cK * VS_STRIDE + fd4) * 4, gv + goff);
    }
    CP_ASYNC_COMMIT();
    cp_async_wait<0>();
    __syncthreads();

    // Q fragments (ldmatrix; QP holds tf32 bits)
    uint32_t qa[8][4];
#pragma unroll
    for (int ks = 0; ks < 8; ks++) ldsm4(qa[ks], a_base + ks * 32);

    float o[8][4];
#pragma unroll
    for (int nt = 0; nt < 8; nt++)
#pragma unroll
        for (int j = 0; j < 4; j++) o[nt][j] = 0.0f;
    float m0r = -1e30f, m1r = -1e30f, l0 = 0.0f, l1 = 0.0f;

    const int r0g = q0 + qrow + gid;
    const int r1g = r0g + 8;
    const int wrow_max = q0 + qrow + 15;

    const int nkt = 2 * qt + 2;
    for (int kt = 0; kt < nkt; kt++) {
        const int k0g = kt * 64;
        const int cur = kt & 1;
        const bool have_next = (kt + 1 < nkt);

        if (have_next) {
            const size_t nb = base + (size_t)(k0g + 64) * 64;
            const uint32_t ksn = ks_u + (cur ^ 1) * KS_SZ * 4;
            const uint32_t vsn = vs_u + (cur ^ 1) * VS_SZ * 4;
#pragma unroll
            for (int i = 0; i < 4; i++) {
                const int cK = fcK + i * 16;
                const size_t goff = nb + (size_t)cK * 64 + fd4;
                cp_async16(ksn + (cK * KS_STRIDE + fd4) * 4, gk + goff);
                cp_async16(vsn + (cK * VS_STRIDE + fd4) * 4, gv + goff);
            }
            CP_ASYNC_COMMIT();
            cp_async_wait<1>();
        } else {
            cp_async_wait<0>();
        }
        __syncthreads();

        if (k0g <= wrow_max) {
            const uint32_t kb = ks_u + cur * KS_SZ * 4 + kb_base;
            const uint32_t* Vs = VsB + cur * VS_SZ;

            // S = Q K^T
            float sc[8][4];
#pragma unroll
            for (int nt = 0; nt < 8; nt++)
#pragma unroll
                for (int j = 0; j < 4; j++) sc[nt][j] = 0.0f;
#pragma unroll
            for (int ks = 0; ks < 8; ks++) {
#pragma unroll
                for (int p = 0; p < 4; p++) {
                    uint32_t br[4];
                    ldsm4(br, kb + p * (16 * KS_STRIDE * 4) + ks * 32);
                    mma_tf32(sc[2 * p],     qa[ks], br[0], br[1]);
                    mma_tf32(sc[2 * p + 1], qa[ks], br[2], br[3]);
                }
            }

            const float scale = 0.125f;
            if (kt >= 2 * qt) {
#pragma unroll
                for (int nt = 0; nt < 8; nt++) {
                    const int col = k0g + nt * 8 + 2 * tg;
                    sc[nt][0] = (col     > r0g) ? -1e30f : sc[nt][0] * scale;
                    sc[nt][1] = (col + 1 > r0g) ? -1e30f : sc[nt][1] * scale;
                    sc[nt][2] = (col     > r1g) ? -1e30f : sc[nt][2] * scale;
                    sc[nt][3] = (col + 1 > r1g) ? -1e30f : sc[nt][3] * scale;
                }
            } else {
#pragma unroll
                for (int nt = 0; nt < 8; nt++)
#pragma unroll
                    for (int j = 0; j < 4; j++) sc[nt][j] *= scale;
            }

            float mx0 = -1e30f, mx1 = -1e30f;
#pragma unroll
            for (int nt = 0; nt < 8; nt++) {
                mx0 = fmaxf(mx0, fmaxf(sc[nt][0], sc[nt][1]));
                mx1 = fmaxf(mx1, fmaxf(sc[nt][2], sc[nt][3]));
            }
            mx0 = fmaxf(mx0, __shfl_xor_sync(0xffffffffu, mx0, 1));
            mx0 = fmaxf(mx0, __shfl_xor_sync(0xffffffffu, mx0, 2));
            mx1 = fmaxf(mx1, __shfl_xor_sync(0xffffffffu, mx1, 1));
            mx1 = fmaxf(mx1, __shfl_xor_sync(0xffffffffu, mx1, 2));

            const float mn0 = fmaxf(m0r, mx0);
            const float mn1 = fmaxf(m1r, mx1);
            const float al0 = __expf(m0r - mn0);
            const float al1 = __expf(m1r - mn1);
            m0r = mn0; m1r = mn1;

            float rs0 = 0.0f, rs1 = 0.0f;
            const int pbase = (qrow + gid) * KS_STRIDE + 2 * tg;
#pragma unroll
            for (int nt = 0; nt < 8; nt++) {
                float p0 = __expf(sc[nt][0] - mn0);
                float p1 = __expf(sc[nt][1] - mn0);
                float p2 = __expf(sc[nt][2] - mn1);
                float p3 = __expf(sc[nt][3] - mn1);
                rs0 += p0 + p1;
                rs1 += p2 + p3;
                uint2 u01; u01.x = f2tf32(p0); u01.y = f2tf32(p1);
                uint2 u23; u23.x = f2tf32(p2); u23.y = f2tf32(p3);
                *(uint2*)&QP[pbase + nt * 8]                 = u01;
                *(uint2*)&QP[pbase + nt * 8 + 8 * KS_STRIDE] = u23;
            }
            rs0 += __shfl_xor_sync(0xffffffffu, rs0, 1);
            rs0 += __shfl_xor_sync(0xffffffffu, rs0, 2);
            rs1 += __shfl_xor_sync(0xffffffffu, rs1, 1);
            rs1 += __shfl_xor_sync(0xffffffffu, rs1, 2);
            l0 = l0 * al0 + rs0;
            l1 = l1 * al1 + rs1;

#pragma unroll
            for (int nt = 0; nt < 8; nt++) {
                o[nt][0] *= al0; o[nt][1] *= al0;
                o[nt][2] *= al1; o[nt][3] *= al1;
            }
            __syncwarp();   // P rows are warp-private

            // O += P V
#pragma unroll
            for (int ks = 0; ks < 8; ks++) {
                uint32_t pa[4];
                ldsm4(pa, a_base + ks * 32);
#pragma unroll
                for (int nt = 0; nt < 8; nt++) {
                    uint32_t b0 = Vs[(ks * 8 + tg) * VS_STRIDE + nt * 8 + gid];
                    uint32_t b1 = Vs[(ks * 8 + tg + 4) * VS_STRIDE + nt * 8 + gid];
                    mma_tf32(o[nt], pa, b0, b1);
                }
            }
        }
        __syncthreads();
    }

    // epilogue: normalize + write ctx [s][b][d] (tf32-rounded for O-GEMM)
    const float inv0 = 1.0f / l0;
    const float inv1 = 1.0f / l1;
#pragma unroll
    for (int nt = 0; nt < 8; nt++) {
        const int col = h * 64 + nt * 8 + 2 * tg;
        float2 v0, v1;
        v0.x = rnd_tf32(o[nt][0] * inv0); v0.y = rnd_tf32(o[nt][1] * inv0);
        v1.x = rnd_tf32(o[nt][2] * inv1); v1.y = rnd_tf32(o[nt][3] * inv1);
        *(float2*)&ctx[((size_t)r0g * BATCH + b) * DMODEL + col] = v0;
        *(float2*)&ctx[((size_t)r1g * BATCH + b) * DMODEL + col] = v1;
    }
}

// ---------------------------------------------------------------------------
extern "C" void kernel_launch(void* const* d_in, const int* in_sizes, int n_in,
                              void* d_out, int out_size)
{
    (void)in_sizes; (void)n_in; (void)out_size;
    const float* Q    = (const float*)d_in[0];
    const float* K    = (const float*)d_in[1];
    const float* V    = (const float*)d_in[2];
    const float* W_q  = (const float*)d_in[3];
    const float* b_q  = (const float*)d_in[4];
    const float* W_k  = (const float*)d_in[5];
    const float* b_k  = (const float*)d_in[6];
    const float* W_v  = (const float*)d_in[7];
    const float* b_v  = (const float*)d_in[8];
    const float* W_o  = (const float*)d_in[9];
    const float* b_o  = (const float*)d_in[10];
    const float* qcos = (const float*)d_in[11];
    const float* qsin = (const float*)d_in[12];
    const float* kcos = (const float*)d_in[13];
    const float* ksin = (const float*)d_in[14];
    float* out = (float*)d_out;

    float *gq, *gk, *gv, *gctx;
    cudaGetSymbolAddress((void**)&gq,   g_q);
    cudaGetSymbolAddress((void**)&gk,   g_k);
    cudaGetSymbolAddress((void**)&gv,   g_v);
    cudaGetSymbolAddress((void**)&gctx, g_ctx);

    cudaFuncSetAttribute(attn_tc,
                         cudaFuncAttributeMaxDynamicSharedMemorySize,
                         ATTN_SMEM_BYTES);
    cudaFuncSetAttribute(gemm_qkv,
                         cudaFuncAttributeMaxDynamicSharedMemorySize,
                         GEMM_SMEM_BYTES);
    cudaFuncSetAttribute(gemm_out,
                         cudaFuncAttributeMaxDynamicSharedMemorySize,
                         GEMM_SMEM_BYTES);

    dim3 qkv_grid(DMODEL / 128, NROWS / 128, 3);   // (8, 32, 3)
    gemm_qkv<<<qkv_grid, 256, GEMM_SMEM_BYTES>>>(
        Q, W_q, b_q, gq, K, W_k, b_k, gk, V, W_v, b_v, gv,
        qcos, qsin, kcos, ksin);

    dim3 agrid(SLEN / QTILE, BATCH * NHEAD);   // (16, 32)
    attn_tc<<<agrid, 256, ATTN_SMEM_BYTES>>>(gq, gk, gv, gctx);

    dim3 ogrid(DMODEL / 128, NROWS / 128);     // (8, 32)
    gemm_out<<<ogrid, 256, GEMM_SMEM_BYTES>>>(gctx, W_o, b_o, out);
}